// round 5
// baseline (speedup 1.0000x reference)
#include <cuda_runtime.h>
#include <cuda_bf16.h>
#include <mma.h>
using namespace nvcuda;

#define NN 100000
#define NPAD 100032   // padded rows so wmma stores never go OOB of each array
#define EE 1600000

// ---------------- scratch (static device globals; no allocation) ----------------
__device__ __align__(16) float g_h0[NPAD * 64];
__device__ __align__(16) float g_xl[NPAD * 64];
__device__ __align__(16) float g_xr[NPAD * 64];
__device__ __align__(16) float g_wcat[128 * 192];
__device__ int   g_cnt[NN];
__device__ float g_sumw[NN];
__device__ int   g_fill[NN];
__device__ int   g_rowptr[NN + 1];
__device__ int2  g_csr[EE];
__device__ int   g_bsum[128];
__device__ int   g_boff[128];
__device__ int   g_is64;

// ---------------- dtype detection: int64 edge_index => odd 32-bit words are all 0 ----------------
__global__ void k_detect(const int* __restrict__ ei32) {
    if (threadIdx.x == 0 && blockIdx.x == 0) {
        int all0 = 1;
        #pragma unroll
        for (int j = 0; j < 8; j++)
            if (ei32[2 * j + 1] != 0) all0 = 0;
        g_is64 = all0;
    }
}

__device__ __forceinline__ int load_idx(const void* ei, int pos) {
    if (g_is64) return (int)((const long long*)ei)[pos];
    return ((const int*)ei)[pos];
}

// ---------------- init ----------------
__global__ void k_zero() {
    int i = blockIdx.x * blockDim.x + threadIdx.x;
    if (i < NN) { g_cnt[i] = 0; g_sumw[i] = 0.f; g_fill[i] = 0; }
}

// ---------------- composite weight: wcat = [W_pre | W_pre@W_l | W_pre@W_r] ----------------
__global__ void k_build_wcat(const float* __restrict__ W_pre,
                             const float* __restrict__ W_l,
                             const float* __restrict__ W_r) {
    int k = blockIdx.x;        // 0..127
    int j = threadIdx.x;       // 0..191
    float v;
    if (j < 64) {
        v = W_pre[k * 64 + j];
    } else {
        const float* W = (j < 128) ? W_l : W_r;
        int c = (j < 128) ? (j - 64) : (j - 128);
        float s = 0.f;
        #pragma unroll 8
        for (int m = 0; m < 64; m++) s += W_pre[k * 64 + m] * W[m * 64 + c];
        v = s;
    }
    g_wcat[k * 192 + j] = v;
}

// ---------------- TF32 tensor-core GEMM: [h0 | x_l+b_l | x_r+b_r] = x @ wcat ----------------
// 3xTF32 hi/lo split for ~fp32 accuracy. Block: 256 thr (8 warps), tile 64x192.
__global__ void k_gemm_pre(const float* __restrict__ x,
                           const float* __restrict__ b_l,
                           const float* __restrict__ b_r) {
    __shared__ float xs_hi[64][20], xs_lo[64][20];
    __shared__ float wc_hi[16][196], wc_lo[16][196];
    __shared__ float bias_s[16][196];
    int tid = threadIdx.x;
    int node0 = blockIdx.x * 64;
    int w = tid >> 5;
    int r = w >> 1;         // row tile 0..3 (16 rows each)
    int g = w & 1;          // column half (6 col tiles each)

    for (int idx = tid; idx < 16 * 196; idx += 256) {
        int c = idx % 196;
        float v = 0.f;
        if (c >= 64 && c < 128)       v = b_l[c - 64];
        else if (c >= 128 && c < 192) v = b_r[c - 128];
        bias_s[idx / 196][c] = v;
    }
    __syncthreads();

    wmma::fragment<wmma::accumulator, 16, 16, 8, float> acc[6];
    #pragma unroll
    for (int j = 0; j < 6; j++)
        wmma::load_matrix_sync(acc[j], &bias_s[0][(g * 6 + j) * 16], 196, wmma::mem_row_major);

    for (int kc = 0; kc < 8; kc++) {
        for (int idx = tid; idx < 64 * 16; idx += 256) {
            int rr = idx >> 4, cc = idx & 15;
            int node = node0 + rr;
            float v = (node < NN) ? x[node * 128 + kc * 16 + cc] : 0.f;
            float hi = wmma::__float_to_tf32(v);
            xs_hi[rr][cc] = hi;
            xs_lo[rr][cc] = wmma::__float_to_tf32(v - hi);
        }
        for (int idx = tid; idx < 16 * 192; idx += 256) {
            int rr = idx / 192, cc = idx % 192;
            float v = g_wcat[(kc * 16 + rr) * 192 + cc];
            float hi = wmma::__float_to_tf32(v);
            wc_hi[rr][cc] = hi;
            wc_lo[rr][cc] = wmma::__float_to_tf32(v - hi);
        }
        __syncthreads();
        #pragma unroll
        for (int ks = 0; ks < 2; ks++) {
            wmma::fragment<wmma::matrix_a, 16, 16, 8, wmma::precision::tf32, wmma::row_major> a_hi, a_lo;
            wmma::load_matrix_sync(a_hi, &xs_hi[r * 16][ks * 8], 20);
            wmma::load_matrix_sync(a_lo, &xs_lo[r * 16][ks * 8], 20);
            #pragma unroll
            for (int j = 0; j < 6; j++) {
                wmma::fragment<wmma::matrix_b, 16, 16, 8, wmma::precision::tf32, wmma::row_major> b_hi, b_lo;
                wmma::load_matrix_sync(b_hi, &wc_hi[ks * 8][(g * 6 + j) * 16], 196);
                wmma::load_matrix_sync(b_lo, &wc_lo[ks * 8][(g * 6 + j) * 16], 196);
                wmma::mma_sync(acc[j], a_hi, b_hi, acc[j]);
                wmma::mma_sync(acc[j], a_lo, b_hi, acc[j]);
                wmma::mma_sync(acc[j], a_hi, b_lo, acc[j]);
            }
        }
        __syncthreads();
    }

    #pragma unroll
    for (int j = 0; j < 6; j++) {
        int CT = g * 6 + j;
        float* base; int cofs;
        if (CT < 4)      { base = g_h0; cofs = CT * 16; }
        else if (CT < 8) { base = g_xl; cofs = (CT - 4) * 16; }
        else             { base = g_xr; cofs = (CT - 8) * 16; }
        wmma::store_matrix_sync(&base[(size_t)(node0 + r * 16) * 64 + cofs], acc[j], 64,
                                wmma::mem_row_major);
    }
}

// ---------------- histogram: in-degree + edge-weight sums over dst ----------------
__global__ void k_hist(const void* __restrict__ ei, const float* __restrict__ ew) {
    int e = blockIdx.x * blockDim.x + threadIdx.x;
    if (e >= EE) return;
    int d = load_idx(ei, EE + e);
    atomicAdd(&g_cnt[d], 1);
    atomicAdd(&g_sumw[d], ew[e]);
}

// ---------------- 3-phase exclusive scan of g_cnt -> g_rowptr ----------------
__global__ void k_scan_p1() {
    int base = blockIdx.x * 1024;
    int s = 0;
    #pragma unroll
    for (int j = 0; j < 4; j++) {
        int k = base + threadIdx.x + j * 256;
        if (k < NN) s += g_cnt[k];
    }
    for (int o = 16; o; o >>= 1) s += __shfl_xor_sync(~0u, s, o);
    __shared__ int sh[8];
    if ((threadIdx.x & 31) == 0) sh[threadIdx.x >> 5] = s;
    __syncthreads();
    if (threadIdx.x == 0) {
        int t = 0;
        for (int w = 0; w < 8; w++) t += sh[w];
        g_bsum[blockIdx.x] = t;
    }
}
__global__ void k_scan_p2(int nb) {
    __shared__ int sh[128];
    sh[threadIdx.x] = (threadIdx.x < nb) ? g_bsum[threadIdx.x] : 0;
    __syncthreads();
    if (threadIdx.x == 0) {
        int run = 0;
        for (int b = 0; b < nb; b++) { int t = sh[b]; sh[b] = run; run += t; }
        g_rowptr[NN] = run;
    }
    __syncthreads();
    if (threadIdx.x < nb) g_boff[threadIdx.x] = sh[threadIdx.x];
}
__global__ void k_scan_p3() {
    int base = blockIdx.x * 1024;
    int idx = base + threadIdx.x * 4;
    int v[4];
    #pragma unroll
    for (int j = 0; j < 4; j++) {
        int k = idx + j;
        v[j] = (k < NN) ? g_cnt[k] : 0;
    }
    int s = v[0] + v[1] + v[2] + v[3];
    int lane = threadIdx.x & 31, wid = threadIdx.x >> 5;
    int xval = s;
    for (int o = 1; o < 32; o <<= 1) {
        int y = __shfl_up_sync(~0u, xval, o);
        if (lane >= o) xval += y;
    }
    __shared__ int wsum[8];
    if (lane == 31) wsum[wid] = xval;
    __syncthreads();
    if (wid == 0) {
        int w = (lane < 8) ? wsum[lane] : 0;
        for (int o = 1; o < 8; o <<= 1) {
            int y = __shfl_up_sync(~0u, w, o);
            if (lane >= o) w += y;
        }
        if (lane < 8) wsum[lane] = w;
    }
    __syncthreads();
    int excl = xval - s + (wid > 0 ? wsum[wid - 1] : 0) + g_boff[blockIdx.x];
    #pragma unroll
    for (int j = 0; j < 4; j++) {
        int k = idx + j;
        if (k < NN) g_rowptr[k] = excl;
        excl += v[j];
    }
}

// ---------------- scatter edges into CSR (by dst) ----------------
__global__ void k_scatter(const void* __restrict__ ei, const float* __restrict__ ew) {
    int e = blockIdx.x * blockDim.x + threadIdx.x;
    if (e >= EE) return;
    int d = load_idx(ei, EE + e);
    int s = load_idx(ei, e);
    int pos = g_rowptr[d] + atomicAdd(&g_fill[d], 1);
    g_csr[pos] = make_int2(s, __float_as_int(ew[e]));
}

// ---------------- main edge kernel: warp per node, 2x unrolled for ILP ----------------
__global__ void k_edge(const float* __restrict__ W_edge,
                       const float* __restrict__ att,
                       const float* __restrict__ gat_bias,
                       float* __restrict__ out_h) {
    int warp = (blockIdx.x * blockDim.x + threadIdx.x) >> 5;
    int lane = threadIdx.x & 31;
    if (warp >= NN) return;
    int i = warp;

    const float2* xl2 = (const float2*)g_xl;
    float2 xr = ((const float2*)g_xr)[i * 32 + lane];
    float2 we = ((const float2*)W_edge)[lane];
    float2 at = ((const float2*)att)[lane];

    int start = g_rowptr[i];
    int deg   = g_rowptr[i + 1] - start;
    float ea_self = g_sumw[i] / fmaxf((float)g_cnt[i], 1.0f);

    float den = 0.f, ax = 0.f, ay = 0.f;
    int t = 0;
    for (; t + 2 <= deg; t += 2) {
        int2 p0 = g_csr[start + t];
        int2 p1 = g_csr[start + t + 1];
        float2 a0 = xl2[p0.x * 32 + lane];
        float2 a1 = xl2[p1.x * 32 + lane];
        float ea0 = __int_as_float(p0.y), ea1 = __int_as_float(p1.y);

        float f0x = fmaf(ea0, we.x, a0.x + xr.x);
        float f0y = fmaf(ea0, we.y, a0.y + xr.y);
        float f1x = fmaf(ea1, we.x, a1.x + xr.x);
        float f1y = fmaf(ea1, we.y, a1.y + xr.y);
        f0x = f0x > 0.f ? f0x : 0.2f * f0x;
        f0y = f0y > 0.f ? f0y : 0.2f * f0y;
        f1x = f1x > 0.f ? f1x : 0.2f * f1x;
        f1y = f1y > 0.f ? f1y : 0.2f * f1y;
        float q0 = f0x * at.x + f0y * at.y;
        float q1 = f1x * at.x + f1y * at.y;
        q0 += __shfl_xor_sync(~0u, q0, 1);
        q1 += __shfl_xor_sync(~0u, q1, 1);
        q0 += __shfl_xor_sync(~0u, q0, 2);
        q1 += __shfl_xor_sync(~0u, q1, 2);
        q0 += __shfl_xor_sync(~0u, q0, 4);
        q1 += __shfl_xor_sync(~0u, q1, 4);
        float e0 = __expf(q0);
        float e1 = __expf(q1);
        den += e0 + e1;
        ax = fmaf(e0, a0.x, ax); ax = fmaf(e1, a1.x, ax);
        ay = fmaf(e0, a0.y, ay); ay = fmaf(e1, a1.y, ay);
    }
    for (int u = 0; u < 2; u++) {   // remainder edge (maybe) + self loop
        int s; float ea;
        if (u == 0) {
            if (t >= deg) continue;
            int2 p = g_csr[start + t];
            s = p.x; ea = __int_as_float(p.y);
        } else {
            s = i; ea = ea_self;
        }
        float2 a = xl2[s * 32 + lane];
        float fx = fmaf(ea, we.x, a.x + xr.x);
        float fy = fmaf(ea, we.y, a.y + xr.y);
        fx = fx > 0.f ? fx : 0.2f * fx;
        fy = fy > 0.f ? fy : 0.2f * fy;
        float q = fx * at.x + fy * at.y;
        q += __shfl_xor_sync(~0u, q, 1);
        q += __shfl_xor_sync(~0u, q, 2);
        q += __shfl_xor_sync(~0u, q, 4);
        float ex = __expf(q);
        den += ex;
        ax = fmaf(ex, a.x, ax);
        ay = fmaf(ex, a.y, ay);
    }
    float inv = 1.0f / den;
    float2 gb = ((const float2*)gat_bias)[lane];
    float ox = fmaf(ax, inv, gb.x);
    float oy = fmaf(ay, inv, gb.y);
    ox = ox > 0.f ? ox : expm1f(ox);   // ELU
    oy = oy > 0.f ? oy : expm1f(oy);
    float2 h0v = ((const float2*)g_h0)[i * 32 + lane];
    ((float2*)out_h)[i * 32 + lane] = make_float2(h0v.x + ox, h0v.y + oy);
}

// ---------------- MLP tail: z = relu(h@W1+b1); logits = z@W2+b2 ----------------
__global__ void k_mlp(const float* __restrict__ h,
                      const float* __restrict__ W1, const float* __restrict__ b1,
                      const float* __restrict__ W2, const float* __restrict__ b2,
                      float* __restrict__ logits) {
    __shared__ float hs[64][65];
    __shared__ __align__(16) float W1s[64 * 64];
    __shared__ float W2s[64 * 10];
    __shared__ float b1s[64];
    __shared__ float b2s[16];
    int tid = threadIdx.x;
    int node0 = blockIdx.x * 64;

    for (int idx = tid; idx < 64 * 64; idx += 256) {
        W1s[idx] = W1[idx];
        int r = idx >> 6, c = idx & 63;
        int node = node0 + r;
        hs[r][c] = (node < NN) ? h[node * 64 + c] : 0.f;
    }
    for (int idx = tid; idx < 640; idx += 256) W2s[idx] = W2[idx];
    if (tid < 64) b1s[tid] = b1[tid];
    if (tid < 10) b2s[tid] = b2[tid];
    __syncthreads();

    int tx = tid & 15, ty = tid >> 4;
    int r0 = ty * 4, c0 = tx * 4;
    float acc[4][4];
    #pragma unroll
    for (int i = 0; i < 4; i++)
        #pragma unroll
        for (int j = 0; j < 4; j++) acc[i][j] = 0.f;
    #pragma unroll 8
    for (int k = 0; k < 64; k++) {
        float a[4] = {hs[r0][k], hs[r0 + 1][k], hs[r0 + 2][k], hs[r0 + 3][k]};
        float4 bv = *(const float4*)&W1s[k * 64 + c0];
        float bb[4] = {bv.x, bv.y, bv.z, bv.w};
        #pragma unroll
        for (int i = 0; i < 4; i++)
            #pragma unroll
            for (int j = 0; j < 4; j++)
                acc[i][j] = fmaf(a[i], bb[j], acc[i][j]);
    }
    __syncthreads();
    #pragma unroll
    for (int i = 0; i < 4; i++)
        #pragma unroll
        for (int j = 0; j < 4; j++)
            hs[r0 + i][c0 + j] = fmaxf(acc[i][j] + b1s[c0 + j], 0.f);
    __syncthreads();

    for (int idx = tid; idx < 640; idx += 256) {
        int r = idx / 10, c = idx % 10;
        float s = b2s[c];
        #pragma unroll 8
        for (int k = 0; k < 64; k++) s += hs[r][k] * W2s[k * 10 + c];
        int node = node0 + r;
        if (node < NN) logits[node * 10 + c] = s;
    }
}

// ---------------- launch ----------------
extern "C" void kernel_launch(void* const* d_in, const int* in_sizes, int n_in,
                              void* d_out, int out_size) {
    const float* x        = (const float*)d_in[0];
    const float* ew       = (const float*)d_in[1];
    const float* W_pre    = (const float*)d_in[2];
    const float* W_l      = (const float*)d_in[3];
    const float* b_l      = (const float*)d_in[4];
    const float* W_r      = (const float*)d_in[5];
    const float* b_r      = (const float*)d_in[6];
    const float* att      = (const float*)d_in[7];
    const float* W_edge   = (const float*)d_in[8];
    const float* gat_bias = (const float*)d_in[9];
    const float* W1       = (const float*)d_in[10];
    const float* b1       = (const float*)d_in[11];
    const float* W2       = (const float*)d_in[12];
    const float* b2       = (const float*)d_in[13];
    const void*  ei       = d_in[14];

    float* out_h      = (float*)d_out;
    float* out_logits = (float*)d_out + (size_t)NN * 64;

    const int NB = (NN + 1023) / 1024;  // 98

    k_detect<<<1, 32>>>((const int*)ei);
    k_zero<<<(NN + 255) / 256, 256>>>();
    k_build_wcat<<<128, 192>>>(W_pre, W_l, W_r);
    k_hist<<<(EE + 255) / 256, 256>>>(ei, ew);
    k_scan_p1<<<NB, 256>>>();
    k_scan_p2<<<1, 128>>>(NB);
    k_scan_p3<<<NB, 256>>>();
    k_scatter<<<(EE + 255) / 256, 256>>>(ei, ew);
    k_gemm_pre<<<(NN + 63) / 64, 256>>>(x, b_l, b_r);
    k_edge<<<(NN * 32 + 255) / 256, 256>>>(W_edge, att, gat_bias, out_h);
    k_mlp<<<(NN + 63) / 64, 256>>>(out_h, W1, b1, W2, b2, out_logits);
}

// round 6
// speedup vs baseline: 1.3041x; 1.3041x over previous
#include <cuda_runtime.h>
#include <cuda_bf16.h>
#include <mma.h>
using namespace nvcuda;

#define NN 100000
#define NPAD 100096   // multiple of 128 so wmma stores never go OOB
#define EE 1600000

// ---------------- scratch (static device globals; no allocation) ----------------
__device__ __align__(16) float g_h0[NPAD * 64];
__device__ __align__(16) float g_xl[NPAD * 64];
__device__ __align__(16) float g_xr[NPAD * 64];
__device__ __align__(16) float g_wcat[128 * 192];
__device__ int   g_cnt[NN];
__device__ float g_sumw[NN];
__device__ int   g_fill[NN];
__device__ int   g_rowptr[NN + 1];
__device__ int2  g_csr[EE];
__device__ int   g_bsum[128];
__device__ int   g_boff[128];
__device__ int   g_is64;

// ---------------- dtype detection ----------------
__global__ void k_detect(const int* __restrict__ ei32) {
    if (threadIdx.x == 0 && blockIdx.x == 0) {
        int all0 = 1;
        #pragma unroll
        for (int j = 0; j < 8; j++)
            if (ei32[2 * j + 1] != 0) all0 = 0;
        g_is64 = all0;
    }
}
__device__ __forceinline__ int load_idx(const void* ei, int pos) {
    if (g_is64) return (int)((const long long*)ei)[pos];
    return ((const int*)ei)[pos];
}

// ---------------- init ----------------
__global__ void k_zero() {
    int i = blockIdx.x * blockDim.x + threadIdx.x;
    if (i < NN) { g_cnt[i] = 0; g_sumw[i] = 0.f; g_fill[i] = 0; }
}

// ---------------- composite weight: wcat = [W_pre | W_pre@W_l | W_pre@W_r] ----------------
__global__ void k_build_wcat(const float* __restrict__ W_pre,
                             const float* __restrict__ W_l,
                             const float* __restrict__ W_r) {
    int k = blockIdx.x;
    int j = threadIdx.x;
    float v;
    if (j < 64) {
        v = W_pre[k * 64 + j];
    } else {
        const float* W = (j < 128) ? W_l : W_r;
        int c = (j < 128) ? (j - 64) : (j - 128);
        float s = 0.f;
        #pragma unroll 8
        for (int m = 0; m < 64; m++) s += W_pre[k * 64 + m] * W[m * 64 + c];
        v = s;
    }
    g_wcat[k * 192 + j] = v;
}

// ---------------- bf16 3-term split tensor-core GEMM ----------------
// [h0 | x_l+b_l | x_r+b_r] = x @ wcat. Block tile 128x192, 8 warps (4 row x 2 col).
#define A_STRIDE 40    // bf16 elems per A smem row (80B, conflict-free ldmatrix)
#define B_STRIDE 200   // bf16 elems per B smem row (400B, conflict-free)
__global__ __launch_bounds__(256, 1)
void k_gemm_pre(const float* __restrict__ x,
                const float* __restrict__ b_l,
                const float* __restrict__ b_r) {
    __shared__ __align__(16) char smem[2 * 128 * A_STRIDE * 2 + 2 * 32 * B_STRIDE * 2];
    __nv_bfloat16* Ah = (__nv_bfloat16*)smem;                         // [128][A_STRIDE]
    __nv_bfloat16* Al = Ah + 128 * A_STRIDE;
    __nv_bfloat16* Bh = (__nv_bfloat16*)(smem + 2 * 128 * A_STRIDE * 2);  // [32][B_STRIDE]
    __nv_bfloat16* Bl = Bh + 32 * B_STRIDE;
    float* biasT = (float*)smem;                                      // overlay [16][B_STRIDE]

    int tid = threadIdx.x;
    int node0 = blockIdx.x * 128;
    int w = tid >> 5;
    int wr = w >> 1;    // 0..3: rows wr*32 .. +32
    int wc = w & 1;     // 0..1: cols wc*96 .. +96

    // ---- bias tile into overlay, load into accumulators ----
    for (int idx = tid; idx < 16 * B_STRIDE; idx += 256) {
        int c = idx % B_STRIDE;
        float v = 0.f;
        if (c >= 64 && c < 128)       v = b_l[c - 64];
        else if (c >= 128 && c < 192) v = b_r[c - 128];
        biasT[idx] = v;
    }
    __syncthreads();

    wmma::fragment<wmma::accumulator, 16, 16, 16, float> acc[2][6];
    #pragma unroll
    for (int i = 0; i < 2; i++)
        #pragma unroll
        for (int j = 0; j < 6; j++)
            wmma::load_matrix_sync(acc[i][j], &biasT[wc * 96 + j * 16], B_STRIDE,
                                   wmma::mem_row_major);
    __syncthreads();

    // ---- K loop: 4 chunks of 32 ----
    for (int kc = 0; kc < 4; kc++) {
        // A: 128 rows x 32 cols (float4 loads: 8 per row)
        for (int idx = tid; idx < 128 * 8; idx += 256) {
            int rr = idx >> 3, q = idx & 7;
            int node = node0 + rr;
            float4 v = make_float4(0.f, 0.f, 0.f, 0.f);
            if (node < NN) v = *(const float4*)&x[node * 128 + kc * 32 + q * 4];
            __nv_bfloat16* ph = &Ah[rr * A_STRIDE + q * 4];
            __nv_bfloat16* pl = &Al[rr * A_STRIDE + q * 4];
            float vv[4] = {v.x, v.y, v.z, v.w};
            #pragma unroll
            for (int u = 0; u < 4; u++) {
                __nv_bfloat16 hi = __float2bfloat16(vv[u]);
                ph[u] = hi;
                pl[u] = __float2bfloat16(vv[u] - __bfloat162float(hi));
            }
        }
        // B: 32 rows x 192 cols (float4: 48 per row)
        for (int idx = tid; idx < 32 * 48; idx += 256) {
            int rr = idx / 48, q = idx % 48;
            float4 v = *(const float4*)&g_wcat[(kc * 32 + rr) * 192 + q * 4];
            __nv_bfloat16* ph = &Bh[rr * B_STRIDE + q * 4];
            __nv_bfloat16* pl = &Bl[rr * B_STRIDE + q * 4];
            float vv[4] = {v.x, v.y, v.z, v.w};
            #pragma unroll
            for (int u = 0; u < 4; u++) {
                __nv_bfloat16 hi = __float2bfloat16(vv[u]);
                ph[u] = hi;
                pl[u] = __float2bfloat16(vv[u] - __bfloat162float(hi));
            }
        }
        __syncthreads();

        #pragma unroll
        for (int kf = 0; kf < 2; kf++) {
            wmma::fragment<wmma::matrix_a, 16, 16, 16, __nv_bfloat16, wmma::row_major> ah[2], al[2];
            #pragma unroll
            for (int i = 0; i < 2; i++) {
                wmma::load_matrix_sync(ah[i], &Ah[(wr * 32 + i * 16) * A_STRIDE + kf * 16], A_STRIDE);
                wmma::load_matrix_sync(al[i], &Al[(wr * 32 + i * 16) * A_STRIDE + kf * 16], A_STRIDE);
            }
            #pragma unroll
            for (int j = 0; j < 6; j++) {
                wmma::fragment<wmma::matrix_b, 16, 16, 16, __nv_bfloat16, wmma::row_major> bh, bl;
                wmma::load_matrix_sync(bh, &Bh[(kf * 16) * B_STRIDE + wc * 96 + j * 16], B_STRIDE);
                wmma::load_matrix_sync(bl, &Bl[(kf * 16) * B_STRIDE + wc * 96 + j * 16], B_STRIDE);
                #pragma unroll
                for (int i = 0; i < 2; i++) {
                    wmma::mma_sync(acc[i][j], ah[i], bh, acc[i][j]);
                    wmma::mma_sync(acc[i][j], al[i], bh, acc[i][j]);
                    wmma::mma_sync(acc[i][j], ah[i], bl, acc[i][j]);
                }
            }
        }
        __syncthreads();
    }

    // ---- store ----
    #pragma unroll
    for (int j = 0; j < 6; j++) {
        int CT = wc * 6 + j;
        float* base; int cofs;
        if (CT < 4)      { base = g_h0; cofs = CT * 16; }
        else if (CT < 8) { base = g_xl; cofs = (CT - 4) * 16; }
        else             { base = g_xr; cofs = (CT - 8) * 16; }
        #pragma unroll
        for (int i = 0; i < 2; i++)
            wmma::store_matrix_sync(&base[(size_t)(node0 + wr * 32 + i * 16) * 64 + cofs],
                                    acc[i][j], 64, wmma::mem_row_major);
    }
}

// ---------------- histogram ----------------
__global__ void k_hist(const void* __restrict__ ei, const float* __restrict__ ew) {
    int e = blockIdx.x * blockDim.x + threadIdx.x;
    if (e >= EE) return;
    int d = load_idx(ei, EE + e);
    atomicAdd(&g_cnt[d], 1);
    atomicAdd(&g_sumw[d], ew[e]);
}

// ---------------- 3-phase exclusive scan ----------------
__global__ void k_scan_p1() {
    int base = blockIdx.x * 1024;
    int s = 0;
    #pragma unroll
    for (int j = 0; j < 4; j++) {
        int k = base + threadIdx.x + j * 256;
        if (k < NN) s += g_cnt[k];
    }
    for (int o = 16; o; o >>= 1) s += __shfl_xor_sync(~0u, s, o);
    __shared__ int sh[8];
    if ((threadIdx.x & 31) == 0) sh[threadIdx.x >> 5] = s;
    __syncthreads();
    if (threadIdx.x == 0) {
        int t = 0;
        for (int w = 0; w < 8; w++) t += sh[w];
        g_bsum[blockIdx.x] = t;
    }
}
__global__ void k_scan_p2(int nb) {
    __shared__ int sh[128];
    sh[threadIdx.x] = (threadIdx.x < nb) ? g_bsum[threadIdx.x] : 0;
    __syncthreads();
    if (threadIdx.x == 0) {
        int run = 0;
        for (int b = 0; b < nb; b++) { int t = sh[b]; sh[b] = run; run += t; }
        g_rowptr[NN] = run;
    }
    __syncthreads();
    if (threadIdx.x < nb) g_boff[threadIdx.x] = sh[threadIdx.x];
}
__global__ void k_scan_p3() {
    int base = blockIdx.x * 1024;
    int idx = base + threadIdx.x * 4;
    int v[4];
    #pragma unroll
    for (int j = 0; j < 4; j++) {
        int k = idx + j;
        v[j] = (k < NN) ? g_cnt[k] : 0;
    }
    int s = v[0] + v[1] + v[2] + v[3];
    int lane = threadIdx.x & 31, wid = threadIdx.x >> 5;
    int xval = s;
    for (int o = 1; o < 32; o <<= 1) {
        int y = __shfl_up_sync(~0u, xval, o);
        if (lane >= o) xval += y;
    }
    __shared__ int wsum[8];
    if (lane == 31) wsum[wid] = xval;
    __syncthreads();
    if (wid == 0) {
        int w = (lane < 8) ? wsum[lane] : 0;
        for (int o = 1; o < 8; o <<= 1) {
            int y = __shfl_up_sync(~0u, w, o);
            if (lane >= o) w += y;
        }
        if (lane < 8) wsum[lane] = w;
    }
    __syncthreads();
    int excl = xval - s + (wid > 0 ? wsum[wid - 1] : 0) + g_boff[blockIdx.x];
    #pragma unroll
    for (int j = 0; j < 4; j++) {
        int k = idx + j;
        if (k < NN) g_rowptr[k] = excl;
        excl += v[j];
    }
}

// ---------------- scatter edges into CSR ----------------
__global__ void k_scatter(const void* __restrict__ ei, const float* __restrict__ ew) {
    int e = blockIdx.x * blockDim.x + threadIdx.x;
    if (e >= EE) return;
    int d = load_idx(ei, EE + e);
    int s = load_idx(ei, e);
    int pos = g_rowptr[d] + atomicAdd(&g_fill[d], 1);
    g_csr[pos] = make_int2(s, __float_as_int(ew[e]));
}

// ---------------- main edge kernel ----------------
__global__ void k_edge(const float* __restrict__ W_edge,
                       const float* __restrict__ att,
                       const float* __restrict__ gat_bias,
                       float* __restrict__ out_h) {
    int warp = (blockIdx.x * blockDim.x + threadIdx.x) >> 5;
    int lane = threadIdx.x & 31;
    if (warp >= NN) return;
    int i = warp;

    const float2* xl2 = (const float2*)g_xl;
    float2 xr = ((const float2*)g_xr)[i * 32 + lane];
    float2 we = ((const float2*)W_edge)[lane];
    float2 at = ((const float2*)att)[lane];

    int start = g_rowptr[i];
    int deg   = g_rowptr[i + 1] - start;
    float ea_self = g_sumw[i] / fmaxf((float)g_cnt[i], 1.0f);

    float den = 0.f, ax = 0.f, ay = 0.f;
    int t = 0;
    for (; t + 2 <= deg; t += 2) {
        int2 p0 = g_csr[start + t];
        int2 p1 = g_csr[start + t + 1];
        float2 a0 = xl2[p0.x * 32 + lane];
        float2 a1 = xl2[p1.x * 32 + lane];
        float ea0 = __int_as_float(p0.y), ea1 = __int_as_float(p1.y);

        float f0x = fmaf(ea0, we.x, a0.x + xr.x);
        float f0y = fmaf(ea0, we.y, a0.y + xr.y);
        float f1x = fmaf(ea1, we.x, a1.x + xr.x);
        float f1y = fmaf(ea1, we.y, a1.y + xr.y);
        f0x = f0x > 0.f ? f0x : 0.2f * f0x;
        f0y = f0y > 0.f ? f0y : 0.2f * f0y;
        f1x = f1x > 0.f ? f1x : 0.2f * f1x;
        f1y = f1y > 0.f ? f1y : 0.2f * f1y;
        float q0 = f0x * at.x + f0y * at.y;
        float q1 = f1x * at.x + f1y * at.y;
        q0 += __shfl_xor_sync(~0u, q0, 1);
        q1 += __shfl_xor_sync(~0u, q1, 1);
        q0 += __shfl_xor_sync(~0u, q0, 2);
        q1 += __shfl_xor_sync(~0u, q1, 2);
        q0 += __shfl_xor_sync(~0u, q0, 4);
        q1 += __shfl_xor_sync(~0u, q1, 4);
        float e0 = __expf(q0);
        float e1 = __expf(q1);
        den += e0 + e1;
        ax = fmaf(e0, a0.x, ax); ax = fmaf(e1, a1.x, ax);
        ay = fmaf(e0, a0.y, ay); ay = fmaf(e1, a1.y, ay);
    }
    for (int u = 0; u < 2; u++) {
        int s; float ea;
        if (u == 0) {
            if (t >= deg) continue;
            int2 p = g_csr[start + t];
            s = p.x; ea = __int_as_float(p.y);
        } else {
            s = i; ea = ea_self;
        }
        float2 a = xl2[s * 32 + lane];
        float fx = fmaf(ea, we.x, a.x + xr.x);
        float fy = fmaf(ea, we.y, a.y + xr.y);
        fx = fx > 0.f ? fx : 0.2f * fx;
        fy = fy > 0.f ? fy : 0.2f * fy;
        float q = fx * at.x + fy * at.y;
        q += __shfl_xor_sync(~0u, q, 1);
        q += __shfl_xor_sync(~0u, q, 2);
        q += __shfl_xor_sync(~0u, q, 4);
        float ex = __expf(q);
        den += ex;
        ax = fmaf(ex, a.x, ax);
        ay = fmaf(ex, a.y, ay);
    }
    float inv = 1.0f / den;
    float2 gb = ((const float2*)gat_bias)[lane];
    float ox = fmaf(ax, inv, gb.x);
    float oy = fmaf(ay, inv, gb.y);
    ox = ox > 0.f ? ox : expm1f(ox);
    oy = oy > 0.f ? oy : expm1f(oy);
    float2 h0v = ((const float2*)g_h0)[i * 32 + lane];
    ((float2*)out_h)[i * 32 + lane] = make_float2(h0v.x + ox, h0v.y + oy);
}

// ---------------- MLP tail ----------------
__global__ void k_mlp(const float* __restrict__ h,
                      const float* __restrict__ W1, const float* __restrict__ b1,
                      const float* __restrict__ W2, const float* __restrict__ b2,
                      float* __restrict__ logits) {
    __shared__ float hs[64][65];
    __shared__ __align__(16) float W1s[64 * 64];
    __shared__ float W2s[64 * 10];
    __shared__ float b1s[64];
    __shared__ float b2s[16];
    int tid = threadIdx.x;
    int node0 = blockIdx.x * 64;

    for (int idx = tid; idx < 64 * 64; idx += 256) {
        W1s[idx] = W1[idx];
        int r = idx >> 6, c = idx & 63;
        int node = node0 + r;
        hs[r][c] = (node < NN) ? h[node * 64 + c] : 0.f;
    }
    for (int idx = tid; idx < 640; idx += 256) W2s[idx] = W2[idx];
    if (tid < 64) b1s[tid] = b1[tid];
    if (tid < 10) b2s[tid] = b2[tid];
    __syncthreads();

    int tx = tid & 15, ty = tid >> 4;
    int r0 = ty * 4, c0 = tx * 4;
    float acc[4][4];
    #pragma unroll
    for (int i = 0; i < 4; i++)
        #pragma unroll
        for (int j = 0; j < 4; j++) acc[i][j] = 0.f;
    #pragma unroll 8
    for (int k = 0; k < 64; k++) {
        float a[4] = {hs[r0][k], hs[r0 + 1][k], hs[r0 + 2][k], hs[r0 + 3][k]};
        float4 bv = *(const float4*)&W1s[k * 64 + c0];
        float bb[4] = {bv.x, bv.y, bv.z, bv.w};
        #pragma unroll
        for (int i = 0; i < 4; i++)
            #pragma unroll
            for (int j = 0; j < 4; j++)
                acc[i][j] = fmaf(a[i], bb[j], acc[i][j]);
    }
    __syncthreads();
    #pragma unroll
    for (int i = 0; i < 4; i++)
        #pragma unroll
        for (int j = 0; j < 4; j++)
            hs[r0 + i][c0 + j] = fmaxf(acc[i][j] + b1s[c0 + j], 0.f);
    __syncthreads();

    for (int idx = tid; idx < 640; idx += 256) {
        int r = idx / 10, c = idx % 10;
        float s = b2s[c];
        #pragma unroll 8
        for (int k = 0; k < 64; k++) s += hs[r][k] * W2s[k * 10 + c];
        int node = node0 + r;
        if (node < NN) logits[node * 10 + c] = s;
    }
}

// ---------------- launch ----------------
extern "C" void kernel_launch(void* const* d_in, const int* in_sizes, int n_in,
                              void* d_out, int out_size) {
    const float* x        = (const float*)d_in[0];
    const float* ew       = (const float*)d_in[1];
    const float* W_pre    = (const float*)d_in[2];
    const float* W_l      = (const float*)d_in[3];
    const float* b_l      = (const float*)d_in[4];
    const float* W_r      = (const float*)d_in[5];
    const float* b_r      = (const float*)d_in[6];
    const float* att      = (const float*)d_in[7];
    const float* W_edge   = (const float*)d_in[8];
    const float* gat_bias = (const float*)d_in[9];
    const float* W1       = (const float*)d_in[10];
    const float* b1       = (const float*)d_in[11];
    const float* W2       = (const float*)d_in[12];
    const float* b2       = (const float*)d_in[13];
    const void*  ei       = d_in[14];

    float* out_h      = (float*)d_out;
    float* out_logits = (float*)d_out + (size_t)NN * 64;

    const int NB = (NN + 1023) / 1024;  // 98

    k_detect<<<1, 32>>>((const int*)ei);
    k_zero<<<(NN + 255) / 256, 256>>>();
    k_build_wcat<<<128, 192>>>(W_pre, W_l, W_r);
    k_hist<<<(EE + 255) / 256, 256>>>(ei, ew);
    k_scan_p1<<<NB, 256>>>();
    k_scan_p2<<<1, 128>>>(NB);
    k_scan_p3<<<NB, 256>>>();
    k_scatter<<<(EE + 255) / 256, 256>>>(ei, ew);
    k_gemm_pre<<<(NPAD / 128), 256>>>(x, b_l, b_r);
    k_edge<<<(NN * 32 + 255) / 256, 256>>>(W_edge, att, gat_bias, out_h);
    k_mlp<<<(NN + 63) / 64, 256>>>(out_h, W1, b1, W2, b2, out_logits);
}

// round 7
// speedup vs baseline: 1.3505x; 1.0356x over previous
#include <cuda_runtime.h>
#include <cuda_bf16.h>
#include <mma.h>
using namespace nvcuda;

#define NN 100000
#define NPAD 100096   // multiple of 128 so wmma stores never go OOB
#define EE 1600000

// ---------------- scratch (static device globals; no allocation) ----------------
__device__ __align__(16) float g_h0[NPAD * 64];
__device__ __align__(16) float g_xl[NPAD * 64];
__device__ __align__(16) float g_xr[NPAD * 64];
__device__ __align__(16) float g_wcat[128 * 192];
__device__ int   g_cnt[NN];
__device__ float g_sumw[NN];
__device__ int   g_fill[NN];
__device__ int   g_rowptr[NN + 1];
__device__ int2  g_csr[EE];
__device__ int   g_bsum[128];
__device__ int   g_boff[128];
__device__ int   g_is64;

// ---------------- dtype detection ----------------
__global__ void k_detect(const int* __restrict__ ei32) {
    if (threadIdx.x == 0 && blockIdx.x == 0) {
        int all0 = 1;
        #pragma unroll
        for (int j = 0; j < 8; j++)
            if (ei32[2 * j + 1] != 0) all0 = 0;
        g_is64 = all0;
    }
}

// ---------------- init ----------------
__global__ void k_zero() {
    int i = blockIdx.x * blockDim.x + threadIdx.x;
    if (i < NN) { g_cnt[i] = 0; g_sumw[i] = 0.f; }
}

// ---------------- composite weight: wcat = [W_pre | W_pre@W_l | W_pre@W_r] ----------------
__global__ void k_build_wcat(const float* __restrict__ W_pre,
                             const float* __restrict__ W_l,
                             const float* __restrict__ W_r) {
    int k = blockIdx.x;
    int j = threadIdx.x;
    float v;
    if (j < 64) {
        v = W_pre[k * 64 + j];
    } else {
        const float* W = (j < 128) ? W_l : W_r;
        int c = (j < 128) ? (j - 64) : (j - 128);
        float s = 0.f;
        #pragma unroll 8
        for (int m = 0; m < 64; m++) s += W_pre[k * 64 + m] * W[m * 64 + c];
        v = s;
    }
    g_wcat[k * 192 + j] = v;
}

// ---------------- bf16 3-term split tensor-core GEMM (pre) ----------------
#define A_STRIDE 40
#define B_STRIDE 200
__global__ __launch_bounds__(256, 1)
void k_gemm_pre(const float* __restrict__ x,
                const float* __restrict__ b_l,
                const float* __restrict__ b_r) {
    __shared__ __align__(16) char smem[2 * 128 * A_STRIDE * 2 + 2 * 32 * B_STRIDE * 2];
    __nv_bfloat16* Ah = (__nv_bfloat16*)smem;
    __nv_bfloat16* Al = Ah + 128 * A_STRIDE;
    __nv_bfloat16* Bh = (__nv_bfloat16*)(smem + 2 * 128 * A_STRIDE * 2);
    __nv_bfloat16* Bl = Bh + 32 * B_STRIDE;
    float* biasT = (float*)smem;

    int tid = threadIdx.x;
    int node0 = blockIdx.x * 128;
    int w = tid >> 5;
    int wr = w >> 1;
    int wc = w & 1;

    for (int idx = tid; idx < 16 * B_STRIDE; idx += 256) {
        int c = idx % B_STRIDE;
        float v = 0.f;
        if (c >= 64 && c < 128)       v = b_l[c - 64];
        else if (c >= 128 && c < 192) v = b_r[c - 128];
        biasT[idx] = v;
    }
    __syncthreads();

    wmma::fragment<wmma::accumulator, 16, 16, 16, float> acc[2][6];
    #pragma unroll
    for (int i = 0; i < 2; i++)
        #pragma unroll
        for (int j = 0; j < 6; j++)
            wmma::load_matrix_sync(acc[i][j], &biasT[wc * 96 + j * 16], B_STRIDE,
                                   wmma::mem_row_major);
    __syncthreads();

    for (int kc = 0; kc < 4; kc++) {
        for (int idx = tid; idx < 128 * 8; idx += 256) {
            int rr = idx >> 3, q = idx & 7;
            int node = node0 + rr;
            float4 v = make_float4(0.f, 0.f, 0.f, 0.f);
            if (node < NN) v = *(const float4*)&x[node * 128 + kc * 32 + q * 4];
            __nv_bfloat16* ph = &Ah[rr * A_STRIDE + q * 4];
            __nv_bfloat16* pl = &Al[rr * A_STRIDE + q * 4];
            float vv[4] = {v.x, v.y, v.z, v.w};
            #pragma unroll
            for (int u = 0; u < 4; u++) {
                __nv_bfloat16 hi = __float2bfloat16(vv[u]);
                ph[u] = hi;
                pl[u] = __float2bfloat16(vv[u] - __bfloat162float(hi));
            }
        }
        for (int idx = tid; idx < 32 * 48; idx += 256) {
            int rr = idx / 48, q = idx % 48;
            float4 v = *(const float4*)&g_wcat[(kc * 32 + rr) * 192 + q * 4];
            __nv_bfloat16* ph = &Bh[rr * B_STRIDE + q * 4];
            __nv_bfloat16* pl = &Bl[rr * B_STRIDE + q * 4];
            float vv[4] = {v.x, v.y, v.z, v.w};
            #pragma unroll
            for (int u = 0; u < 4; u++) {
                __nv_bfloat16 hi = __float2bfloat16(vv[u]);
                ph[u] = hi;
                pl[u] = __float2bfloat16(vv[u] - __bfloat162float(hi));
            }
        }
        __syncthreads();

        #pragma unroll
        for (int kf = 0; kf < 2; kf++) {
            wmma::fragment<wmma::matrix_a, 16, 16, 16, __nv_bfloat16, wmma::row_major> ah[2], al[2];
            #pragma unroll
            for (int i = 0; i < 2; i++) {
                wmma::load_matrix_sync(ah[i], &Ah[(wr * 32 + i * 16) * A_STRIDE + kf * 16], A_STRIDE);
                wmma::load_matrix_sync(al[i], &Al[(wr * 32 + i * 16) * A_STRIDE + kf * 16], A_STRIDE);
            }
            #pragma unroll
            for (int j = 0; j < 6; j++) {
                wmma::fragment<wmma::matrix_b, 16, 16, 16, __nv_bfloat16, wmma::row_major> bh, bl;
                wmma::load_matrix_sync(bh, &Bh[(kf * 16) * B_STRIDE + wc * 96 + j * 16], B_STRIDE);
                wmma::load_matrix_sync(bl, &Bl[(kf * 16) * B_STRIDE + wc * 96 + j * 16], B_STRIDE);
                #pragma unroll
                for (int i = 0; i < 2; i++) {
                    wmma::mma_sync(acc[i][j], ah[i], bh, acc[i][j]);
                    wmma::mma_sync(acc[i][j], al[i], bh, acc[i][j]);
                    wmma::mma_sync(acc[i][j], ah[i], bl, acc[i][j]);
                }
            }
        }
        __syncthreads();
    }

    #pragma unroll
    for (int j = 0; j < 6; j++) {
        int CT = wc * 6 + j;
        float* base; int cofs;
        if (CT < 4)      { base = g_h0; cofs = CT * 16; }
        else if (CT < 8) { base = g_xl; cofs = (CT - 4) * 16; }
        else             { base = g_xr; cofs = (CT - 8) * 16; }
        #pragma unroll
        for (int i = 0; i < 2; i++)
            wmma::store_matrix_sync(&base[(size_t)(node0 + wr * 32 + i * 16) * 64 + cofs],
                                    acc[i][j], 64, wmma::mem_row_major);
    }
}

// ---------------- histogram: 2 edges/thread ----------------
__global__ void k_hist(const void* __restrict__ ei, const float* __restrict__ ew) {
    int e = (blockIdx.x * blockDim.x + threadIdx.x) * 2;
    if (e >= EE) return;
    int d0, d1;
    if (g_is64) {
        d0 = (int)((const long long*)ei)[EE + e];
        d1 = (int)((const long long*)ei)[EE + e + 1];
    } else {
        int2 dd = *(const int2*)((const int*)ei + EE + e);
        d0 = dd.x; d1 = dd.y;
    }
    float2 w = *(const float2*)&ew[e];
    atomicAdd(&g_cnt[d0], 1);
    atomicAdd(&g_sumw[d0], w.x);
    atomicAdd(&g_cnt[d1], 1);
    atomicAdd(&g_sumw[d1], w.y);
}

// ---------------- 3-phase exclusive scan; p3 also seeds g_fill = rowptr ----------------
__global__ void k_scan_p1() {
    int base = blockIdx.x * 1024;
    int s = 0;
    #pragma unroll
    for (int j = 0; j < 4; j++) {
        int k = base + threadIdx.x + j * 256;
        if (k < NN) s += g_cnt[k];
    }
    for (int o = 16; o; o >>= 1) s += __shfl_xor_sync(~0u, s, o);
    __shared__ int sh[8];
    if ((threadIdx.x & 31) == 0) sh[threadIdx.x >> 5] = s;
    __syncthreads();
    if (threadIdx.x == 0) {
        int t = 0;
        for (int w = 0; w < 8; w++) t += sh[w];
        g_bsum[blockIdx.x] = t;
    }
}
__global__ void k_scan_p2(int nb) {
    __shared__ int sh[128];
    sh[threadIdx.x] = (threadIdx.x < nb) ? g_bsum[threadIdx.x] : 0;
    __syncthreads();
    if (threadIdx.x == 0) {
        int run = 0;
        for (int b = 0; b < nb; b++) { int t = sh[b]; sh[b] = run; run += t; }
        g_rowptr[NN] = run;
    }
    __syncthreads();
    if (threadIdx.x < nb) g_boff[threadIdx.x] = sh[threadIdx.x];
}
__global__ void k_scan_p3() {
    int base = blockIdx.x * 1024;
    int idx = base + threadIdx.x * 4;
    int v[4];
    #pragma unroll
    for (int j = 0; j < 4; j++) {
        int k = idx + j;
        v[j] = (k < NN) ? g_cnt[k] : 0;
    }
    int s = v[0] + v[1] + v[2] + v[3];
    int lane = threadIdx.x & 31, wid = threadIdx.x >> 5;
    int xval = s;
    for (int o = 1; o < 32; o <<= 1) {
        int y = __shfl_up_sync(~0u, xval, o);
        if (lane >= o) xval += y;
    }
    __shared__ int wsum[8];
    if (lane == 31) wsum[wid] = xval;
    __syncthreads();
    if (wid == 0) {
        int w = (lane < 8) ? wsum[lane] : 0;
        for (int o = 1; o < 8; o <<= 1) {
            int y = __shfl_up_sync(~0u, w, o);
            if (lane >= o) w += y;
        }
        if (lane < 8) wsum[lane] = w;
    }
    __syncthreads();
    int excl = xval - s + (wid > 0 ? wsum[wid - 1] : 0) + g_boff[blockIdx.x];
    #pragma unroll
    for (int j = 0; j < 4; j++) {
        int k = idx + j;
        if (k < NN) { g_rowptr[k] = excl; g_fill[k] = excl; }
        excl += v[j];
    }
}

// ---------------- scatter edges into CSR: 2 edges/thread, g_fill pre-seeded ----------------
__global__ void k_scatter(const void* __restrict__ ei, const float* __restrict__ ew) {
    int e = (blockIdx.x * blockDim.x + threadIdx.x) * 2;
    if (e >= EE) return;
    int s0, s1, d0, d1;
    if (g_is64) {
        const long long* e64 = (const long long*)ei;
        s0 = (int)e64[e];      s1 = (int)e64[e + 1];
        d0 = (int)e64[EE + e]; d1 = (int)e64[EE + e + 1];
    } else {
        const int* e32 = (const int*)ei;
        int2 ss = *(const int2*)(e32 + e);
        int2 dd = *(const int2*)(e32 + EE + e);
        s0 = ss.x; s1 = ss.y; d0 = dd.x; d1 = dd.y;
    }
    float2 w = *(const float2*)&ew[e];
    int p0 = atomicAdd(&g_fill[d0], 1);
    g_csr[p0] = make_int2(s0, __float_as_int(w.x));
    int p1 = atomicAdd(&g_fill[d1], 1);
    g_csr[p1] = make_int2(s1, __float_as_int(w.y));
}

// ---------------- main edge kernel: 16 lanes/node (float4), 2 nodes/warp ----------------
__global__ void k_edge(const float* __restrict__ W_edge,
                       const float* __restrict__ att,
                       const float* __restrict__ gat_bias,
                       float* __restrict__ out_h) {
    int warp = (blockIdx.x * blockDim.x + threadIdx.x) >> 5;
    int lane = threadIdx.x & 31;
    int half = lane >> 4, sl = lane & 15;
    int i = warp * 2 + half;
    if (i >= NN) return;

    const float4* xl4 = (const float4*)g_xl;
    float4 xr = ((const float4*)g_xr)[i * 16 + sl];
    float4 we = ((const float4*)W_edge)[sl];
    float4 at = ((const float4*)att)[sl];

    int start = g_rowptr[i];
    int deg   = g_rowptr[i + 1] - start;
    float ea_self = g_sumw[i] / fmaxf((float)g_cnt[i], 1.0f);

    float den = 0.f;
    float a0 = 0.f, a1 = 0.f, a2 = 0.f, a3 = 0.f;

    int t = 0;
    for (; t + 2 <= deg; t += 2) {
        int2 p0 = g_csr[start + t];
        int2 p1 = g_csr[start + t + 1];
        float4 x0 = xl4[p0.x * 16 + sl];
        float4 x1 = xl4[p1.x * 16 + sl];
        float ea0 = __int_as_float(p0.y), ea1 = __int_as_float(p1.y);

        float f0x = fmaf(ea0, we.x, x0.x + xr.x);
        float f0y = fmaf(ea0, we.y, x0.y + xr.y);
        float f0z = fmaf(ea0, we.z, x0.z + xr.z);
        float f0w = fmaf(ea0, we.w, x0.w + xr.w);
        float f1x = fmaf(ea1, we.x, x1.x + xr.x);
        float f1y = fmaf(ea1, we.y, x1.y + xr.y);
        float f1z = fmaf(ea1, we.z, x1.z + xr.z);
        float f1w = fmaf(ea1, we.w, x1.w + xr.w);
        f0x = f0x > 0.f ? f0x : 0.2f * f0x;  f0y = f0y > 0.f ? f0y : 0.2f * f0y;
        f0z = f0z > 0.f ? f0z : 0.2f * f0z;  f0w = f0w > 0.f ? f0w : 0.2f * f0w;
        f1x = f1x > 0.f ? f1x : 0.2f * f1x;  f1y = f1y > 0.f ? f1y : 0.2f * f1y;
        f1z = f1z > 0.f ? f1z : 0.2f * f1z;  f1w = f1w > 0.f ? f1w : 0.2f * f1w;
        float q0 = f0x * at.x + f0y * at.y + f0z * at.z + f0w * at.w;
        float q1 = f1x * at.x + f1y * at.y + f1z * at.z + f1w * at.w;
        q0 += __shfl_xor_sync(~0u, q0, 1);
        q1 += __shfl_xor_sync(~0u, q1, 1);
        q0 += __shfl_xor_sync(~0u, q0, 2);
        q1 += __shfl_xor_sync(~0u, q1, 2);
        float e0 = __expf(q0);
        float e1 = __expf(q1);
        den += e0 + e1;
        a0 = fmaf(e0, x0.x, a0); a0 = fmaf(e1, x1.x, a0);
        a1 = fmaf(e0, x0.y, a1); a1 = fmaf(e1, x1.y, a1);
        a2 = fmaf(e0, x0.z, a2); a2 = fmaf(e1, x1.z, a2);
        a3 = fmaf(e0, x0.w, a3); a3 = fmaf(e1, x1.w, a3);
    }
    for (int u = 0; u < 2; u++) {   // remainder edge (maybe) + self loop
        int s; float ea;
        if (u == 0) {
            if (t >= deg) continue;
            int2 p = g_csr[start + t];
            s = p.x; ea = __int_as_float(p.y);
        } else {
            s = i; ea = ea_self;
        }
        float4 xv = xl4[s * 16 + sl];
        float fx = fmaf(ea, we.x, xv.x + xr.x);
        float fy = fmaf(ea, we.y, xv.y + xr.y);
        float fz = fmaf(ea, we.z, xv.z + xr.z);
        float fw = fmaf(ea, we.w, xv.w + xr.w);
        fx = fx > 0.f ? fx : 0.2f * fx;  fy = fy > 0.f ? fy : 0.2f * fy;
        fz = fz > 0.f ? fz : 0.2f * fz;  fw = fw > 0.f ? fw : 0.2f * fw;
        float q = fx * at.x + fy * at.y + fz * at.z + fw * at.w;
        q += __shfl_xor_sync(~0u, q, 1);
        q += __shfl_xor_sync(~0u, q, 2);
        float ex = __expf(q);
        den += ex;
        a0 = fmaf(ex, xv.x, a0);
        a1 = fmaf(ex, xv.y, a1);
        a2 = fmaf(ex, xv.z, a2);
        a3 = fmaf(ex, xv.w, a3);
    }
    float inv = 1.0f / den;
    float4 gb = ((const float4*)gat_bias)[sl];
    float o0 = fmaf(a0, inv, gb.x);
    float o1 = fmaf(a1, inv, gb.y);
    float o2 = fmaf(a2, inv, gb.z);
    float o3 = fmaf(a3, inv, gb.w);
    o0 = o0 > 0.f ? o0 : expm1f(o0);
    o1 = o1 > 0.f ? o1 : expm1f(o1);
    o2 = o2 > 0.f ? o2 : expm1f(o2);
    o3 = o3 > 0.f ? o3 : expm1f(o3);
    float4 h0v = ((const float4*)g_h0)[i * 16 + sl];
    ((float4*)out_h)[i * 16 + sl] =
        make_float4(h0v.x + o0, h0v.y + o1, h0v.z + o2, h0v.w + o3);
}

// ---------------- MLP tail: layer1 bf16-split wmma, layer2 SIMT ----------------
#define MS 66
__global__ __launch_bounds__(256)
void k_mlp(const float* __restrict__ h,
           const float* __restrict__ W1, const float* __restrict__ b1,
           const float* __restrict__ W2, const float* __restrict__ b2,
           float* __restrict__ logits) {
    __shared__ __align__(16) char sm[64 * MS * 2 * 2 * 2];   // W1 region + H region
    __nv_bfloat16* W1h = (__nv_bfloat16*)sm;
    __nv_bfloat16* W1l = W1h + 64 * MS;
    __nv_bfloat16* Hh  = (__nv_bfloat16*)(sm + 64 * MS * 4);
    __nv_bfloat16* Hl  = Hh + 64 * MS;
    float* zs = (float*)(sm + 64 * MS * 4);                  // overlay H region after GEMM
    __shared__ float W2s[64 * 10];
    __shared__ float b1s[64];
    __shared__ float b2s[16];

    int tid = threadIdx.x;
    int node0 = blockIdx.x * 64;
    int w = tid >> 5;
    int wr = w >> 1;    // 0..3
    int wc = w & 1;     // 0..1

    for (int idx = tid; idx < 64 * 64; idx += 256) {
        int r = idx >> 6, c = idx & 63;
        float wv = W1[idx];
        __nv_bfloat16 whi = __float2bfloat16(wv);
        W1h[r * MS + c] = whi;
        W1l[r * MS + c] = __float2bfloat16(wv - __bfloat162float(whi));
        int node = node0 + r;
        float hv = (node < NN) ? h[node * 64 + c] : 0.f;
        __nv_bfloat16 hhi = __float2bfloat16(hv);
        Hh[r * MS + c] = hhi;
        Hl[r * MS + c] = __float2bfloat16(hv - __bfloat162float(hhi));
    }
    for (int idx = tid; idx < 640; idx += 256) W2s[idx] = W2[idx];
    if (tid < 64) b1s[tid] = b1[tid];
    if (tid < 10) b2s[tid] = b2[tid];
    __syncthreads();

    wmma::fragment<wmma::accumulator, 16, 16, 16, float> acc[2];
    wmma::fill_fragment(acc[0], 0.f);
    wmma::fill_fragment(acc[1], 0.f);
    #pragma unroll
    for (int kf = 0; kf < 4; kf++) {
        wmma::fragment<wmma::matrix_a, 16, 16, 16, __nv_bfloat16, wmma::row_major> ah, al;
        wmma::load_matrix_sync(ah, &Hh[(wr * 16) * MS + kf * 16], MS);
        wmma::load_matrix_sync(al, &Hl[(wr * 16) * MS + kf * 16], MS);
        #pragma unroll
        for (int j = 0; j < 2; j++) {
            wmma::fragment<wmma::matrix_b, 16, 16, 16, __nv_bfloat16, wmma::row_major> bh, bl;
            wmma::load_matrix_sync(bh, &W1h[(kf * 16) * MS + wc * 32 + j * 16], MS);
            wmma::load_matrix_sync(bl, &W1l[(kf * 16) * MS + wc * 32 + j * 16], MS);
            wmma::mma_sync(acc[j], ah, bh, acc[j]);
            wmma::mma_sync(acc[j], al, bh, acc[j]);
            wmma::mma_sync(acc[j], ah, bl, acc[j]);
        }
    }
    __syncthreads();   // all H reads done before overlay write
    #pragma unroll
    for (int j = 0; j < 2; j++)
        wmma::store_matrix_sync(&zs[(wr * 16) * MS + wc * 32 + j * 16], acc[j], MS,
                                wmma::mem_row_major);
    __syncthreads();
    // relu + bias in place
    for (int idx = tid; idx < 64 * 64; idx += 256) {
        int r = idx >> 6, c = idx & 63;
        zs[r * MS + c] = fmaxf(zs[r * MS + c] + b1s[c], 0.f);
    }
    __syncthreads();
    // layer 2
    for (int idx = tid; idx < 640; idx += 256) {
        int r = idx / 10, c = idx % 10;
        float s = b2s[c];
        #pragma unroll 8
        for (int k = 0; k < 64; k++) s += zs[r * MS + k] * W2s[k * 10 + c];
        int node = node0 + r;
        if (node < NN) logits[node * 10 + c] = s;
    }
}

// ---------------- launch ----------------
extern "C" void kernel_launch(void* const* d_in, const int* in_sizes, int n_in,
                              void* d_out, int out_size) {
    const float* x        = (const float*)d_in[0];
    const float* ew       = (const float*)d_in[1];
    const float* W_pre    = (const float*)d_in[2];
    const float* W_l      = (const float*)d_in[3];
    const float* b_l      = (const float*)d_in[4];
    const float* W_r      = (const float*)d_in[5];
    const float* b_r      = (const float*)d_in[6];
    const float* att      = (const float*)d_in[7];
    const float* W_edge   = (const float*)d_in[8];
    const float* gat_bias = (const float*)d_in[9];
    const float* W1       = (const float*)d_in[10];
    const float* b1       = (const float*)d_in[11];
    const float* W2       = (const float*)d_in[12];
    const float* b2       = (const float*)d_in[13];
    const void*  ei       = d_in[14];

    float* out_h      = (float*)d_out;
    float* out_logits = (float*)d_out + (size_t)NN * 64;

    const int NB = (NN + 1023) / 1024;  // 98

    k_detect<<<1, 32>>>((const int*)ei);
    k_zero<<<(NN + 255) / 256, 256>>>();
    k_build_wcat<<<128, 192>>>(W_pre, W_l, W_r);
    k_hist<<<(EE / 2 + 255) / 256, 256>>>(ei, ew);
    k_scan_p1<<<NB, 256>>>();
    k_scan_p2<<<1, 128>>>(NB);
    k_scan_p3<<<NB, 256>>>();
    k_scatter<<<(EE / 2 + 255) / 256, 256>>>(ei, ew);
    k_gemm_pre<<<(NPAD / 128), 256>>>(x, b_l, b_r);
    k_edge<<<((NN + 1) / 2 * 32 + 255) / 256, 256>>>(W_edge, att, gat_bias, out_h);
    k_mlp<<<(NN + 63) / 64, 256>>>(out_h, W1, b1, W2, b2, out_logits);
}

// round 8
// speedup vs baseline: 1.4567x; 1.0786x over previous
#include <cuda_runtime.h>
#include <cuda_bf16.h>
#include <mma.h>
using namespace nvcuda;

#define NN 100000
#define NPAD 100096   // multiple of 128 so wmma stores never go OOB
#define EE 1600000

// ---------------- scratch (static device globals; no allocation) ----------------
__device__ __align__(16) float g_h0[NPAD * 64];
__device__ __align__(16) float g_xl[NPAD * 64];
__device__ __align__(16) float g_xr[NPAD * 64];
__device__ __align__(16) float g_wcat[128 * 192];
__device__ int   g_cnt[NN];
__device__ float g_sumw[NN];
__device__ int   g_fill[NN];
__device__ int   g_rowptr[NN + 1];
__device__ int2  g_csr[EE];
__device__ int   g_bsum[128];
__device__ int   g_boff[128];
__device__ int   g_is64;

// ---------------- dtype detection ----------------
__global__ void k_detect(const int* __restrict__ ei32) {
    if (threadIdx.x == 0 && blockIdx.x == 0) {
        int all0 = 1;
        #pragma unroll
        for (int j = 0; j < 8; j++)
            if (ei32[2 * j + 1] != 0) all0 = 0;
        g_is64 = all0;
    }
}

// ---------------- composite weight: wcat = [W_pre | W_pre@W_l | W_pre@W_r] ----------------
__global__ void k_build_wcat(const float* __restrict__ W_pre,
                             const float* __restrict__ W_l,
                             const float* __restrict__ W_r) {
    int k = blockIdx.x;
    int j = threadIdx.x;
    float v;
    if (j < 64) {
        v = W_pre[k * 64 + j];
    } else {
        const float* W = (j < 128) ? W_l : W_r;
        int c = (j < 128) ? (j - 64) : (j - 128);
        float s = 0.f;
        #pragma unroll 8
        for (int m = 0; m < 64; m++) s += W_pre[k * 64 + m] * W[m * 64 + c];
        v = s;
    }
    g_wcat[k * 192 + j] = v;
}

// ---------------- bf16 3-term split tensor-core GEMM (pre) ----------------
#define A_STRIDE 40
#define B_STRIDE 200
__global__ __launch_bounds__(256, 1)
void k_gemm_pre(const float* __restrict__ x,
                const float* __restrict__ b_l,
                const float* __restrict__ b_r) {
    __shared__ __align__(16) char smem[2 * 128 * A_STRIDE * 2 + 2 * 32 * B_STRIDE * 2];
    __nv_bfloat16* Ah = (__nv_bfloat16*)smem;
    __nv_bfloat16* Al = Ah + 128 * A_STRIDE;
    __nv_bfloat16* Bh = (__nv_bfloat16*)(smem + 2 * 128 * A_STRIDE * 2);
    __nv_bfloat16* Bl = Bh + 32 * B_STRIDE;
    float* biasT = (float*)smem;

    int tid = threadIdx.x;
    int node0 = blockIdx.x * 128;
    int w = tid >> 5;
    int wr = w >> 1;
    int wc = w & 1;

    for (int idx = tid; idx < 16 * B_STRIDE; idx += 256) {
        int c = idx % B_STRIDE;
        float v = 0.f;
        if (c >= 64 && c < 128)       v = b_l[c - 64];
        else if (c >= 128 && c < 192) v = b_r[c - 128];
        biasT[idx] = v;
    }
    __syncthreads();

    wmma::fragment<wmma::accumulator, 16, 16, 16, float> acc[2][6];
    #pragma unroll
    for (int i = 0; i < 2; i++)
        #pragma unroll
        for (int j = 0; j < 6; j++)
            wmma::load_matrix_sync(acc[i][j], &biasT[wc * 96 + j * 16], B_STRIDE,
                                   wmma::mem_row_major);
    __syncthreads();

    for (int kc = 0; kc < 4; kc++) {
        for (int idx = tid; idx < 128 * 8; idx += 256) {
            int rr = idx >> 3, q = idx & 7;
            int node = node0 + rr;
            float4 v = make_float4(0.f, 0.f, 0.f, 0.f);
            if (node < NN) v = *(const float4*)&x[node * 128 + kc * 32 + q * 4];
            __nv_bfloat16* ph = &Ah[rr * A_STRIDE + q * 4];
            __nv_bfloat16* pl = &Al[rr * A_STRIDE + q * 4];
            float vv[4] = {v.x, v.y, v.z, v.w};
            #pragma unroll
            for (int u = 0; u < 4; u++) {
                __nv_bfloat16 hi = __float2bfloat16(vv[u]);
                ph[u] = hi;
                pl[u] = __float2bfloat16(vv[u] - __bfloat162float(hi));
            }
        }
        for (int idx = tid; idx < 32 * 48; idx += 256) {
            int rr = idx / 48, q = idx % 48;
            float4 v = *(const float4*)&g_wcat[(kc * 32 + rr) * 192 + q * 4];
            __nv_bfloat16* ph = &Bh[rr * B_STRIDE + q * 4];
            __nv_bfloat16* pl = &Bl[rr * B_STRIDE + q * 4];
            float vv[4] = {v.x, v.y, v.z, v.w};
            #pragma unroll
            for (int u = 0; u < 4; u++) {
                __nv_bfloat16 hi = __float2bfloat16(vv[u]);
                ph[u] = hi;
                pl[u] = __float2bfloat16(vv[u] - __bfloat162float(hi));
            }
        }
        __syncthreads();

        #pragma unroll
        for (int kf = 0; kf < 2; kf++) {
            wmma::fragment<wmma::matrix_a, 16, 16, 16, __nv_bfloat16, wmma::row_major> ah[2], al[2];
            #pragma unroll
            for (int i = 0; i < 2; i++) {
                wmma::load_matrix_sync(ah[i], &Ah[(wr * 32 + i * 16) * A_STRIDE + kf * 16], A_STRIDE);
                wmma::load_matrix_sync(al[i], &Al[(wr * 32 + i * 16) * A_STRIDE + kf * 16], A_STRIDE);
            }
            #pragma unroll
            for (int j = 0; j < 6; j++) {
                wmma::fragment<wmma::matrix_b, 16, 16, 16, __nv_bfloat16, wmma::row_major> bh, bl;
                wmma::load_matrix_sync(bh, &Bh[(kf * 16) * B_STRIDE + wc * 96 + j * 16], B_STRIDE);
                wmma::load_matrix_sync(bl, &Bl[(kf * 16) * B_STRIDE + wc * 96 + j * 16], B_STRIDE);
                #pragma unroll
                for (int i = 0; i < 2; i++) {
                    wmma::mma_sync(acc[i][j], ah[i], bh, acc[i][j]);
                    wmma::mma_sync(acc[i][j], al[i], bh, acc[i][j]);
                    wmma::mma_sync(acc[i][j], ah[i], bl, acc[i][j]);
                }
            }
        }
        __syncthreads();
    }

    #pragma unroll
    for (int j = 0; j < 6; j++) {
        int CT = wc * 6 + j;
        float* base; int cofs;
        if (CT < 4)      { base = g_h0; cofs = CT * 16; }
        else if (CT < 8) { base = g_xl; cofs = (CT - 4) * 16; }
        else             { base = g_xr; cofs = (CT - 8) * 16; }
        #pragma unroll
        for (int i = 0; i < 2; i++)
            wmma::store_matrix_sync(&base[(size_t)(node0 + wr * 32 + i * 16) * 64 + cofs],
                                    acc[i][j], 64, wmma::mem_row_major);
    }
}

// ---------------- histogram: 2 edges/thread ----------------
__global__ void k_hist(const void* __restrict__ ei, const float* __restrict__ ew) {
    int e = (blockIdx.x * blockDim.x + threadIdx.x) * 2;
    if (e >= EE) return;
    int d0, d1;
    if (g_is64) {
        d0 = (int)((const long long*)ei)[EE + e];
        d1 = (int)((const long long*)ei)[EE + e + 1];
    } else {
        int2 dd = *(const int2*)((const int*)ei + EE + e);
        d0 = dd.x; d1 = dd.y;
    }
    float2 w = *(const float2*)&ew[e];
    atomicAdd(&g_cnt[d0], 1);
    atomicAdd(&g_sumw[d0], w.x);
    atomicAdd(&g_cnt[d1], 1);
    atomicAdd(&g_sumw[d1], w.y);
}

// ---------------- 3-phase exclusive scan; p3 also seeds g_fill = rowptr ----------------
__global__ void k_scan_p1() {
    int base = blockIdx.x * 1024;
    int s = 0;
    #pragma unroll
    for (int j = 0; j < 4; j++) {
        int k = base + threadIdx.x + j * 256;
        if (k < NN) s += g_cnt[k];
    }
    for (int o = 16; o; o >>= 1) s += __shfl_xor_sync(~0u, s, o);
    __shared__ int sh[8];
    if ((threadIdx.x & 31) == 0) sh[threadIdx.x >> 5] = s;
    __syncthreads();
    if (threadIdx.x == 0) {
        int t = 0;
        for (int w = 0; w < 8; w++) t += sh[w];
        g_bsum[blockIdx.x] = t;
    }
}
__global__ void k_scan_p2(int nb) {
    __shared__ int sh[128];
    sh[threadIdx.x] = (threadIdx.x < nb) ? g_bsum[threadIdx.x] : 0;
    __syncthreads();
    if (threadIdx.x == 0) {
        int run = 0;
        for (int b = 0; b < nb; b++) { int t = sh[b]; sh[b] = run; run += t; }
        g_rowptr[NN] = run;
    }
    __syncthreads();
    if (threadIdx.x < nb) g_boff[threadIdx.x] = sh[threadIdx.x];
}
__global__ void k_scan_p3() {
    int base = blockIdx.x * 1024;
    int idx = base + threadIdx.x * 4;
    int v[4];
    #pragma unroll
    for (int j = 0; j < 4; j++) {
        int k = idx + j;
        v[j] = (k < NN) ? g_cnt[k] : 0;
    }
    int s = v[0] + v[1] + v[2] + v[3];
    int lane = threadIdx.x & 31, wid = threadIdx.x >> 5;
    int xval = s;
    for (int o = 1; o < 32; o <<= 1) {
        int y = __shfl_up_sync(~0u, xval, o);
        if (lane >= o) xval += y;
    }
    __shared__ int wsum[8];
    if (lane == 31) wsum[wid] = xval;
    __syncthreads();
    if (wid == 0) {
        int w = (lane < 8) ? wsum[lane] : 0;
        for (int o = 1; o < 8; o <<= 1) {
            int y = __shfl_up_sync(~0u, w, o);
            if (lane >= o) w += y;
        }
        if (lane < 8) wsum[lane] = w;
    }
    __syncthreads();
    int excl = xval - s + (wid > 0 ? wsum[wid - 1] : 0) + g_boff[blockIdx.x];
    #pragma unroll
    for (int j = 0; j < 4; j++) {
        int k = idx + j;
        if (k < NN) { g_rowptr[k] = excl; g_fill[k] = excl; }
        excl += v[j];
    }
}

// ---------------- scatter edges into CSR: 2 edges/thread, g_fill pre-seeded ----------------
__global__ void k_scatter(const void* __restrict__ ei, const float* __restrict__ ew) {
    int e = (blockIdx.x * blockDim.x + threadIdx.x) * 2;
    if (e >= EE) return;
    int s0, s1, d0, d1;
    if (g_is64) {
        const long long* e64 = (const long long*)ei;
        s0 = (int)e64[e];      s1 = (int)e64[e + 1];
        d0 = (int)e64[EE + e]; d1 = (int)e64[EE + e + 1];
    } else {
        const int* e32 = (const int*)ei;
        int2 ss = *(const int2*)(e32 + e);
        int2 dd = *(const int2*)(e32 + EE + e);
        s0 = ss.x; s1 = ss.y; d0 = dd.x; d1 = dd.y;
    }
    float2 w = *(const float2*)&ew[e];
    int p0 = atomicAdd(&g_fill[d0], 1);
    g_csr[p0] = make_int2(s0, __float_as_int(w.x));
    int p1 = atomicAdd(&g_fill[d1], 1);
    g_csr[p1] = make_int2(s1, __float_as_int(w.y));
}

// ---------------- main edge kernel: 16 lanes/node (float4), 2 nodes/warp ----------------
__global__ void k_edge(const float* __restrict__ W_edge,
                       const float* __restrict__ att,
                       const float* __restrict__ gat_bias,
                       float* __restrict__ out_h) {
    int warp = (blockIdx.x * blockDim.x + threadIdx.x) >> 5;
    int lane = threadIdx.x & 31;
    int half = lane >> 4, sl = lane & 15;
    int i = warp * 2 + half;
    if (i >= NN) return;

    const float4* xl4 = (const float4*)g_xl;
    float4 xr = ((const float4*)g_xr)[i * 16 + sl];
    float4 we = ((const float4*)W_edge)[sl];
    float4 at = ((const float4*)att)[sl];

    int start = g_rowptr[i];
    int deg   = g_rowptr[i + 1] - start;
    float ea_self = g_sumw[i] / fmaxf((float)g_cnt[i], 1.0f);

    float den = 0.f;
    float a0 = 0.f, a1 = 0.f, a2 = 0.f, a3 = 0.f;

    int t = 0;
    for (; t + 2 <= deg; t += 2) {
        int2 p0 = g_csr[start + t];
        int2 p1 = g_csr[start + t + 1];
        float4 x0 = xl4[p0.x * 16 + sl];
        float4 x1 = xl4[p1.x * 16 + sl];
        float ea0 = __int_as_float(p0.y), ea1 = __int_as_float(p1.y);

        float f0x = fmaf(ea0, we.x, x0.x + xr.x);
        float f0y = fmaf(ea0, we.y, x0.y + xr.y);
        float f0z = fmaf(ea0, we.z, x0.z + xr.z);
        float f0w = fmaf(ea0, we.w, x0.w + xr.w);
        float f1x = fmaf(ea1, we.x, x1.x + xr.x);
        float f1y = fmaf(ea1, we.y, x1.y + xr.y);
        float f1z = fmaf(ea1, we.z, x1.z + xr.z);
        float f1w = fmaf(ea1, we.w, x1.w + xr.w);
        f0x = f0x > 0.f ? f0x : 0.2f * f0x;  f0y = f0y > 0.f ? f0y : 0.2f * f0y;
        f0z = f0z > 0.f ? f0z : 0.2f * f0z;  f0w = f0w > 0.f ? f0w : 0.2f * f0w;
        f1x = f1x > 0.f ? f1x : 0.2f * f1x;  f1y = f1y > 0.f ? f1y : 0.2f * f1y;
        f1z = f1z > 0.f ? f1z : 0.2f * f1z;  f1w = f1w > 0.f ? f1w : 0.2f * f1w;
        float q0 = f0x * at.x + f0y * at.y + f0z * at.z + f0w * at.w;
        float q1 = f1x * at.x + f1y * at.y + f1z * at.z + f1w * at.w;
        q0 += __shfl_xor_sync(~0u, q0, 1);
        q1 += __shfl_xor_sync(~0u, q1, 1);
        q0 += __shfl_xor_sync(~0u, q0, 2);
        q1 += __shfl_xor_sync(~0u, q1, 2);
        float e0 = __expf(q0);
        float e1 = __expf(q1);
        den += e0 + e1;
        a0 = fmaf(e0, x0.x, a0); a0 = fmaf(e1, x1.x, a0);
        a1 = fmaf(e0, x0.y, a1); a1 = fmaf(e1, x1.y, a1);
        a2 = fmaf(e0, x0.z, a2); a2 = fmaf(e1, x1.z, a2);
        a3 = fmaf(e0, x0.w, a3); a3 = fmaf(e1, x1.w, a3);
    }
    for (int u = 0; u < 2; u++) {   // remainder edge (maybe) + self loop
        int s; float ea;
        if (u == 0) {
            if (t >= deg) continue;
            int2 p = g_csr[start + t];
            s = p.x; ea = __int_as_float(p.y);
        } else {
            s = i; ea = ea_self;
        }
        float4 xv = xl4[s * 16 + sl];
        float fx = fmaf(ea, we.x, xv.x + xr.x);
        float fy = fmaf(ea, we.y, xv.y + xr.y);
        float fz = fmaf(ea, we.z, xv.z + xr.z);
        float fw = fmaf(ea, we.w, xv.w + xr.w);
        fx = fx > 0.f ? fx : 0.2f * fx;  fy = fy > 0.f ? fy : 0.2f * fy;
        fz = fz > 0.f ? fz : 0.2f * fz;  fw = fw > 0.f ? fw : 0.2f * fw;
        float q = fx * at.x + fy * at.y + fz * at.z + fw * at.w;
        q += __shfl_xor_sync(~0u, q, 1);
        q += __shfl_xor_sync(~0u, q, 2);
        float ex = __expf(q);
        den += ex;
        a0 = fmaf(ex, xv.x, a0);
        a1 = fmaf(ex, xv.y, a1);
        a2 = fmaf(ex, xv.z, a2);
        a3 = fmaf(ex, xv.w, a3);
    }
    float inv = 1.0f / den;
    float4 gb = ((const float4*)gat_bias)[sl];
    float o0 = fmaf(a0, inv, gb.x);
    float o1 = fmaf(a1, inv, gb.y);
    float o2 = fmaf(a2, inv, gb.z);
    float o3 = fmaf(a3, inv, gb.w);
    o0 = o0 > 0.f ? o0 : expm1f(o0);
    o1 = o1 > 0.f ? o1 : expm1f(o1);
    o2 = o2 > 0.f ? o2 : expm1f(o2);
    o3 = o3 > 0.f ? o3 : expm1f(o3);
    float4 h0v = ((const float4*)g_h0)[i * 16 + sl];
    ((float4*)out_h)[i * 16 + sl] =
        make_float4(h0v.x + o0, h0v.y + o1, h0v.z + o2, h0v.w + o3);
}

// ---------------- MLP tail: layer1 bf16-split wmma, layer2 SIMT ----------------
#define MS 66
__global__ __launch_bounds__(256)
void k_mlp(const float* __restrict__ h,
           const float* __restrict__ W1, const float* __restrict__ b1,
           const float* __restrict__ W2, const float* __restrict__ b2,
           float* __restrict__ logits) {
    __shared__ __align__(16) char sm[64 * MS * 2 * 2 * 2];
    __nv_bfloat16* W1h = (__nv_bfloat16*)sm;
    __nv_bfloat16* W1l = W1h + 64 * MS;
    __nv_bfloat16* Hh  = (__nv_bfloat16*)(sm + 64 * MS * 4);
    __nv_bfloat16* Hl  = Hh + 64 * MS;
    float* zs = (float*)(sm + 64 * MS * 4);
    __shared__ float W2s[64 * 10];
    __shared__ float b1s[64];
    __shared__ float b2s[16];

    int tid = threadIdx.x;
    int node0 = blockIdx.x * 64;
    int w = tid >> 5;
    int wr = w >> 1;
    int wc = w & 1;

    for (int idx = tid; idx < 64 * 64; idx += 256) {
        int r = idx >> 6, c = idx & 63;
        float wv = W1[idx];
        __nv_bfloat16 whi = __float2bfloat16(wv);
        W1h[r * MS + c] = whi;
        W1l[r * MS + c] = __float2bfloat16(wv - __bfloat162float(whi));
        int node = node0 + r;
        float hv = (node < NN) ? h[node * 64 + c] : 0.f;
        __nv_bfloat16 hhi = __float2bfloat16(hv);
        Hh[r * MS + c] = hhi;
        Hl[r * MS + c] = __float2bfloat16(hv - __bfloat162float(hhi));
    }
    for (int idx = tid; idx < 640; idx += 256) W2s[idx] = W2[idx];
    if (tid < 64) b1s[tid] = b1[tid];
    if (tid < 10) b2s[tid] = b2[tid];
    __syncthreads();

    wmma::fragment<wmma::accumulator, 16, 16, 16, float> acc[2];
    wmma::fill_fragment(acc[0], 0.f);
    wmma::fill_fragment(acc[1], 0.f);
    #pragma unroll
    for (int kf = 0; kf < 4; kf++) {
        wmma::fragment<wmma::matrix_a, 16, 16, 16, __nv_bfloat16, wmma::row_major> ah, al;
        wmma::load_matrix_sync(ah, &Hh[(wr * 16) * MS + kf * 16], MS);
        wmma::load_matrix_sync(al, &Hl[(wr * 16) * MS + kf * 16], MS);
        #pragma unroll
        for (int j = 0; j < 2; j++) {
            wmma::fragment<wmma::matrix_b, 16, 16, 16, __nv_bfloat16, wmma::row_major> bh, bl;
            wmma::load_matrix_sync(bh, &W1h[(kf * 16) * MS + wc * 32 + j * 16], MS);
            wmma::load_matrix_sync(bl, &W1l[(kf * 16) * MS + wc * 32 + j * 16], MS);
            wmma::mma_sync(acc[j], ah, bh, acc[j]);
            wmma::mma_sync(acc[j], al, bh, acc[j]);
            wmma::mma_sync(acc[j], ah, bl, acc[j]);
        }
    }
    __syncthreads();
    #pragma unroll
    for (int j = 0; j < 2; j++)
        wmma::store_matrix_sync(&zs[(wr * 16) * MS + wc * 32 + j * 16], acc[j], MS,
                                wmma::mem_row_major);
    __syncthreads();
    for (int idx = tid; idx < 64 * 64; idx += 256) {
        int r = idx >> 6, c = idx & 63;
        zs[r * MS + c] = fmaxf(zs[r * MS + c] + b1s[c], 0.f);
    }
    __syncthreads();
    for (int idx = tid; idx < 640; idx += 256) {
        int r = idx / 10, c = idx % 10;
        float s = b2s[c];
        #pragma unroll 8
        for (int k = 0; k < 64; k++) s += zs[r * MS + k] * W2s[k * 10 + c];
        int node = node0 + r;
        if (node < NN) logits[node * 10 + c] = s;
    }
}

// ---------------- launch: fork-join two streams inside the captured graph ----------------
static cudaStream_t s_csr = nullptr;
static cudaEvent_t  ev_fork = nullptr, ev_join = nullptr;
static void* a_cnt  = nullptr;
static void* a_sumw = nullptr;

extern "C" void kernel_launch(void* const* d_in, const int* in_sizes, int n_in,
                              void* d_out, int out_size) {
    const float* x        = (const float*)d_in[0];
    const float* ew       = (const float*)d_in[1];
    const float* W_pre    = (const float*)d_in[2];
    const float* W_l      = (const float*)d_in[3];
    const float* b_l      = (const float*)d_in[4];
    const float* W_r      = (const float*)d_in[5];
    const float* b_r      = (const float*)d_in[6];
    const float* att      = (const float*)d_in[7];
    const float* W_edge   = (const float*)d_in[8];
    const float* gat_bias = (const float*)d_in[9];
    const float* W1       = (const float*)d_in[10];
    const float* b1       = (const float*)d_in[11];
    const float* W2       = (const float*)d_in[12];
    const float* b2       = (const float*)d_in[13];
    const void*  ei       = d_in[14];

    float* out_h      = (float*)d_out;
    float* out_logits = (float*)d_out + (size_t)NN * 64;

    // One-time host-side setup (first call is the non-captured correctness run).
    if (s_csr == nullptr) {
        cudaStreamCreateWithFlags(&s_csr, cudaStreamNonBlocking);
        cudaEventCreateWithFlags(&ev_fork, cudaEventDisableTiming);
        cudaEventCreateWithFlags(&ev_join, cudaEventDisableTiming);
        cudaGetSymbolAddress(&a_cnt, g_cnt);
        cudaGetSymbolAddress(&a_sumw, g_sumw);
    }

    const int NB = (NN + 1023) / 1024;  // 98

    // --- legacy stream: dtype detect, then fork ---
    k_detect<<<1, 32>>>((const int*)ei);
    cudaEventRecord(ev_fork, 0);
    cudaStreamWaitEvent(s_csr, ev_fork, 0);

    // --- side stream: CSR build chain ---
    cudaMemsetAsync(a_cnt, 0, NN * sizeof(int), s_csr);
    cudaMemsetAsync(a_sumw, 0, NN * sizeof(float), s_csr);
    k_hist<<<(EE / 2 + 255) / 256, 256, 0, s_csr>>>(ei, ew);
    k_scan_p1<<<NB, 256, 0, s_csr>>>();
    k_scan_p2<<<1, 128, 0, s_csr>>>(NB);
    k_scan_p3<<<NB, 256, 0, s_csr>>>();
    k_scatter<<<(EE / 2 + 255) / 256, 256, 0, s_csr>>>(ei, ew);
    cudaEventRecord(ev_join, s_csr);

    // --- legacy stream (concurrent with CSR chain): GEMM chain ---
    k_build_wcat<<<128, 192>>>(W_pre, W_l, W_r);
    k_gemm_pre<<<(NPAD / 128), 256>>>(x, b_l, b_r);

    // --- join, then edge + mlp ---
    cudaStreamWaitEvent(0, ev_join, 0);
    k_edge<<<((NN + 1) / 2 * 32 + 255) / 256, 256>>>(W_edge, att, gat_bias, out_h);
    k_mlp<<<(NN + 63) / 64, 256>>>(out_h, W1, b1, W2, b2, out_logits);
}

// round 9
// speedup vs baseline: 1.4717x; 1.0103x over previous
#include <cuda_runtime.h>
#include <cuda_bf16.h>
#include <mma.h>
using namespace nvcuda;

#define NN 100000
#define NPAD 100096   // multiple of 128 so wmma stores never go OOB
#define EE 1600000
#define NBLK 98       // scan tiles: ceil(NN/1024)

// ---------------- scratch (static device globals; no allocation) ----------------
__device__ __align__(16) float g_h0[NPAD * 64];
__device__ __align__(16) float g_xl[NPAD * 64];
__device__ __align__(16) float g_xr[NPAD * 64];
__device__ __align__(16) float g_wcat[128 * 192];
__device__ int   g_cnt[NN];
__device__ int   g_fill[NN];
__device__ int   g_rowptr[NN + 1];
__device__ int2  g_csr[EE];
__device__ unsigned g_scan_stat[NBLK + 1];   // [0..NBLK-1] flagged prefix, [NBLK] tile counter
__device__ int   g_is64;

// ---------------- dtype detection: int64 edge_index => odd 32-bit words all 0 ----------------
__global__ void k_detect(const int* __restrict__ ei32) {
    int lane = threadIdx.x;
    int v = (lane < 16) ? ei32[lane] : 0;
    int bad = (lane < 16) && (lane & 1) && (v != 0);
    unsigned m = __ballot_sync(~0u, bad);
    if (lane == 0) g_is64 = (m == 0);
}

// ---------------- composite weight: wcat = [W_pre | W_pre@W_l | W_pre@W_r] ----------------
__global__ void k_build_wcat(const float* __restrict__ W_pre,
                             const float* __restrict__ W_l,
                             const float* __restrict__ W_r) {
    int k = blockIdx.x;
    int j = threadIdx.x;
    float v;
    if (j < 64) {
        v = W_pre[k * 64 + j];
    } else {
        const float* W = (j < 128) ? W_l : W_r;
        int c = (j < 128) ? (j - 64) : (j - 128);
        float s = 0.f;
        #pragma unroll 8
        for (int m = 0; m < 64; m++) s += W_pre[k * 64 + m] * W[m * 64 + c];
        v = s;
    }
    g_wcat[k * 192 + j] = v;
}

// ---------------- bf16 3-term split tensor-core GEMM (pre) ----------------
#define A_STRIDE 40
#define B_STRIDE 200
__global__ __launch_bounds__(256, 1)
void k_gemm_pre(const float* __restrict__ x,
                const float* __restrict__ b_l,
                const float* __restrict__ b_r) {
    __shared__ __align__(16) char smem[2 * 128 * A_STRIDE * 2 + 2 * 32 * B_STRIDE * 2];
    __nv_bfloat16* Ah = (__nv_bfloat16*)smem;
    __nv_bfloat16* Al = Ah + 128 * A_STRIDE;
    __nv_bfloat16* Bh = (__nv_bfloat16*)(smem + 2 * 128 * A_STRIDE * 2);
    __nv_bfloat16* Bl = Bh + 32 * B_STRIDE;
    float* biasT = (float*)smem;

    int tid = threadIdx.x;
    int node0 = blockIdx.x * 128;
    int w = tid >> 5;
    int wr = w >> 1;
    int wc = w & 1;

    for (int idx = tid; idx < 16 * B_STRIDE; idx += 256) {
        int c = idx % B_STRIDE;
        float v = 0.f;
        if (c >= 64 && c < 128)       v = b_l[c - 64];
        else if (c >= 128 && c < 192) v = b_r[c - 128];
        biasT[idx] = v;
    }
    __syncthreads();

    wmma::fragment<wmma::accumulator, 16, 16, 16, float> acc[2][6];
    #pragma unroll
    for (int i = 0; i < 2; i++)
        #pragma unroll
        for (int j = 0; j < 6; j++)
            wmma::load_matrix_sync(acc[i][j], &biasT[wc * 96 + j * 16], B_STRIDE,
                                   wmma::mem_row_major);
    __syncthreads();

    for (int kc = 0; kc < 4; kc++) {
        for (int idx = tid; idx < 128 * 8; idx += 256) {
            int rr = idx >> 3, q = idx & 7;
            int node = node0 + rr;
            float4 v = make_float4(0.f, 0.f, 0.f, 0.f);
            if (node < NN) v = *(const float4*)&x[node * 128 + kc * 32 + q * 4];
            __nv_bfloat16* ph = &Ah[rr * A_STRIDE + q * 4];
            __nv_bfloat16* pl = &Al[rr * A_STRIDE + q * 4];
            float vv[4] = {v.x, v.y, v.z, v.w};
            #pragma unroll
            for (int u = 0; u < 4; u++) {
                __nv_bfloat16 hi = __float2bfloat16(vv[u]);
                ph[u] = hi;
                pl[u] = __float2bfloat16(vv[u] - __bfloat162float(hi));
            }
        }
        for (int idx = tid; idx < 32 * 48; idx += 256) {
            int rr = idx / 48, q = idx % 48;
            float4 v = *(const float4*)&g_wcat[(kc * 32 + rr) * 192 + q * 4];
            __nv_bfloat16* ph = &Bh[rr * B_STRIDE + q * 4];
            __nv_bfloat16* pl = &Bl[rr * B_STRIDE + q * 4];
            float vv[4] = {v.x, v.y, v.z, v.w};
            #pragma unroll
            for (int u = 0; u < 4; u++) {
                __nv_bfloat16 hi = __float2bfloat16(vv[u]);
                ph[u] = hi;
                pl[u] = __float2bfloat16(vv[u] - __bfloat162float(hi));
            }
        }
        __syncthreads();

        #pragma unroll
        for (int kf = 0; kf < 2; kf++) {
            wmma::fragment<wmma::matrix_a, 16, 16, 16, __nv_bfloat16, wmma::row_major> ah[2], al[2];
            #pragma unroll
            for (int i = 0; i < 2; i++) {
                wmma::load_matrix_sync(ah[i], &Ah[(wr * 32 + i * 16) * A_STRIDE + kf * 16], A_STRIDE);
                wmma::load_matrix_sync(al[i], &Al[(wr * 32 + i * 16) * A_STRIDE + kf * 16], A_STRIDE);
            }
            #pragma unroll
            for (int j = 0; j < 6; j++) {
                wmma::fragment<wmma::matrix_b, 16, 16, 16, __nv_bfloat16, wmma::row_major> bh, bl;
                wmma::load_matrix_sync(bh, &Bh[(kf * 16) * B_STRIDE + wc * 96 + j * 16], B_STRIDE);
                wmma::load_matrix_sync(bl, &Bl[(kf * 16) * B_STRIDE + wc * 96 + j * 16], B_STRIDE);
                #pragma unroll
                for (int i = 0; i < 2; i++) {
                    wmma::mma_sync(acc[i][j], ah[i], bh, acc[i][j]);
                    wmma::mma_sync(acc[i][j], al[i], bh, acc[i][j]);
                    wmma::mma_sync(acc[i][j], ah[i], bl, acc[i][j]);
                }
            }
        }
        __syncthreads();
    }

    #pragma unroll
    for (int j = 0; j < 6; j++) {
        int CT = wc * 6 + j;
        float* base; int cofs;
        if (CT < 4)      { base = g_h0; cofs = CT * 16; }
        else if (CT < 8) { base = g_xl; cofs = (CT - 4) * 16; }
        else             { base = g_xr; cofs = (CT - 8) * 16; }
        #pragma unroll
        for (int i = 0; i < 2; i++)
            wmma::store_matrix_sync(&base[(size_t)(node0 + wr * 32 + i * 16) * 64 + cofs],
                                    acc[i][j], 64, wmma::mem_row_major);
    }
}

// ---------------- histogram: in-degree only, 2 edges/thread ----------------
__global__ void k_hist(const void* __restrict__ ei) {
    int e = (blockIdx.x * blockDim.x + threadIdx.x) * 2;
    if (e >= EE) return;
    int d0, d1;
    if (g_is64) {
        d0 = (int)((const long long*)ei)[EE + e];
        d1 = (int)((const long long*)ei)[EE + e + 1];
    } else {
        int2 dd = *(const int2*)((const int*)ei + EE + e);
        d0 = dd.x; d1 = dd.y;
    }
    atomicAdd(&g_cnt[d0], 1);
    atomicAdd(&g_cnt[d1], 1);
}

// ---------------- single-kernel decoupled-lookback exclusive scan ----------------
// g_cnt -> g_rowptr (+ g_fill seed + g_rowptr[NN]). g_scan_stat must be zeroed first.
__global__ __launch_bounds__(256)
void k_scan_lb() {
    __shared__ int s_tile;
    __shared__ int s_prefix;
    __shared__ int wsum[8];
    int tid = threadIdx.x;
    if (tid == 0) s_tile = (int)atomicAdd(&g_scan_stat[NBLK], 1u);
    __syncthreads();
    int tile = s_tile;

    int idx = tile * 1024 + tid * 4;
    int v[4];
    #pragma unroll
    for (int j = 0; j < 4; j++) {
        int k = idx + j;
        v[j] = (k < NN) ? g_cnt[k] : 0;
    }
    int s = v[0] + v[1] + v[2] + v[3];
    int lane = tid & 31, wid = tid >> 5;
    int xval = s;
    for (int o = 1; o < 32; o <<= 1) {
        int y = __shfl_up_sync(~0u, xval, o);
        if (lane >= o) xval += y;
    }
    if (lane == 31) wsum[wid] = xval;
    __syncthreads();
    if (wid == 0) {
        int w = (lane < 8) ? wsum[lane] : 0;
        for (int o = 1; o < 8; o <<= 1) {
            int y = __shfl_up_sync(~0u, w, o);
            if (lane >= o) w += y;
        }
        if (lane < 8) wsum[lane] = w;
    }
    __syncthreads();
    int total = wsum[7];

    if (tid == 0) {
        if (tile > 0) {
            // publish aggregate so later tiles don't stall on us
            atomicExch(&g_scan_stat[tile], (unsigned)total | (1u << 30));
            // lookback
            int run = 0;
            int j = tile - 1;
            while (true) {
                unsigned st = *(volatile unsigned*)&g_scan_stat[j];
                unsigned fl = st >> 30;
                if (fl == 0u) continue;
                run += (int)(st & 0x3FFFFFFFu);
                if (fl >= 2u) break;
                j--;
            }
            s_prefix = run;
            atomicExch(&g_scan_stat[tile], (unsigned)(run + total) | (2u << 30));
        } else {
            s_prefix = 0;
            atomicExch(&g_scan_stat[0], (unsigned)total | (2u << 30));
        }
        if (tile == NBLK - 1) g_rowptr[NN] = s_prefix + total;
    }
    __syncthreads();

    int excl = s_prefix + xval - s + (wid > 0 ? wsum[wid - 1] : 0);
    #pragma unroll
    for (int j = 0; j < 4; j++) {
        int k = idx + j;
        if (k < NN) { g_rowptr[k] = excl; g_fill[k] = excl; }
        excl += v[j];
    }
}

// ---------------- scatter edges into CSR: 2 edges/thread, g_fill pre-seeded ----------------
__global__ void k_scatter(const void* __restrict__ ei, const float* __restrict__ ew) {
    int e = (blockIdx.x * blockDim.x + threadIdx.x) * 2;
    if (e >= EE) return;
    int s0, s1, d0, d1;
    if (g_is64) {
        const long long* e64 = (const long long*)ei;
        s0 = (int)e64[e];      s1 = (int)e64[e + 1];
        d0 = (int)e64[EE + e]; d1 = (int)e64[EE + e + 1];
    } else {
        const int* e32 = (const int*)ei;
        int2 ss = *(const int2*)(e32 + e);
        int2 dd = *(const int2*)(e32 + EE + e);
        s0 = ss.x; s1 = ss.y; d0 = dd.x; d1 = dd.y;
    }
    float2 w = *(const float2*)&ew[e];
    int p0 = atomicAdd(&g_fill[d0], 1);
    g_csr[p0] = make_int2(s0, __float_as_int(w.x));
    int p1 = atomicAdd(&g_fill[d1], 1);
    g_csr[p1] = make_int2(s1, __float_as_int(w.y));
}

// ---------------- main edge kernel: 16 lanes/node (float4), 2 nodes/warp ----------------
// Edge-weight sum accumulated inline; self-loop uses mean of accumulated weights.
__global__ void k_edge(const float* __restrict__ W_edge,
                       const float* __restrict__ att,
                       const float* __restrict__ gat_bias,
                       float* __restrict__ out_h) {
    int warp = (blockIdx.x * blockDim.x + threadIdx.x) >> 5;
    int lane = threadIdx.x & 31;
    int half = lane >> 4, sl = lane & 15;
    int i = warp * 2 + half;
    if (i >= NN) return;

    const float4* xl4 = (const float4*)g_xl;
    float4 xr = ((const float4*)g_xr)[i * 16 + sl];
    float4 we = ((const float4*)W_edge)[sl];
    float4 at = ((const float4*)att)[sl];

    int start = g_rowptr[i];
    int deg   = g_rowptr[i + 1] - start;

    float den = 0.f, sw = 0.f;
    float a0 = 0.f, a1 = 0.f, a2 = 0.f, a3 = 0.f;

    int t = 0;
    for (; t + 2 <= deg; t += 2) {
        int2 p0 = g_csr[start + t];
        int2 p1 = g_csr[start + t + 1];
        float4 x0 = xl4[p0.x * 16 + sl];
        float4 x1 = xl4[p1.x * 16 + sl];
        float ea0 = __int_as_float(p0.y), ea1 = __int_as_float(p1.y);
        sw += ea0 + ea1;

        float f0x = fmaf(ea0, we.x, x0.x + xr.x);
        float f0y = fmaf(ea0, we.y, x0.y + xr.y);
        float f0z = fmaf(ea0, we.z, x0.z + xr.z);
        float f0w = fmaf(ea0, we.w, x0.w + xr.w);
        float f1x = fmaf(ea1, we.x, x1.x + xr.x);
        float f1y = fmaf(ea1, we.y, x1.y + xr.y);
        float f1z = fmaf(ea1, we.z, x1.z + xr.z);
        float f1w = fmaf(ea1, we.w, x1.w + xr.w);
        f0x = f0x > 0.f ? f0x : 0.2f * f0x;  f0y = f0y > 0.f ? f0y : 0.2f * f0y;
        f0z = f0z > 0.f ? f0z : 0.2f * f0z;  f0w = f0w > 0.f ? f0w : 0.2f * f0w;
        f1x = f1x > 0.f ? f1x : 0.2f * f1x;  f1y = f1y > 0.f ? f1y : 0.2f * f1y;
        f1z = f1z > 0.f ? f1z : 0.2f * f1z;  f1w = f1w > 0.f ? f1w : 0.2f * f1w;
        float q0 = f0x * at.x + f0y * at.y + f0z * at.z + f0w * at.w;
        float q1 = f1x * at.x + f1y * at.y + f1z * at.z + f1w * at.w;
        q0 += __shfl_xor_sync(~0u, q0, 1);
        q1 += __shfl_xor_sync(~0u, q1, 1);
        q0 += __shfl_xor_sync(~0u, q0, 2);
        q1 += __shfl_xor_sync(~0u, q1, 2);
        float e0 = __expf(q0);
        float e1 = __expf(q1);
        den += e0 + e1;
        a0 = fmaf(e0, x0.x, a0); a0 = fmaf(e1, x1.x, a0);
        a1 = fmaf(e0, x0.y, a1); a1 = fmaf(e1, x1.y, a1);
        a2 = fmaf(e0, x0.z, a2); a2 = fmaf(e1, x1.z, a2);
        a3 = fmaf(e0, x0.w, a3); a3 = fmaf(e1, x1.w, a3);
    }
    if (t < deg) {   // remainder edge
        int2 p = g_csr[start + t];
        float ea = __int_as_float(p.y);
        sw += ea;
        float4 xv = xl4[p.x * 16 + sl];
        float fx = fmaf(ea, we.x, xv.x + xr.x);
        float fy = fmaf(ea, we.y, xv.y + xr.y);
        float fz = fmaf(ea, we.z, xv.z + xr.z);
        float fw = fmaf(ea, we.w, xv.w + xr.w);
        fx = fx > 0.f ? fx : 0.2f * fx;  fy = fy > 0.f ? fy : 0.2f * fy;
        fz = fz > 0.f ? fz : 0.2f * fz;  fw = fw > 0.f ? fw : 0.2f * fw;
        float q = fx * at.x + fy * at.y + fz * at.z + fw * at.w;
        q += __shfl_xor_sync(~0u, q, 1);
        q += __shfl_xor_sync(~0u, q, 2);
        float ex = __expf(q);
        den += ex;
        a0 = fmaf(ex, xv.x, a0);
        a1 = fmaf(ex, xv.y, a1);
        a2 = fmaf(ex, xv.z, a2);
        a3 = fmaf(ex, xv.w, a3);
    }
    {   // self loop with mean edge weight
        float ea = sw / fmaxf((float)deg, 1.0f);
        float4 xv = xl4[i * 16 + sl];
        float fx = fmaf(ea, we.x, xv.x + xr.x);
        float fy = fmaf(ea, we.y, xv.y + xr.y);
        float fz = fmaf(ea, we.z, xv.z + xr.z);
        float fw = fmaf(ea, we.w, xv.w + xr.w);
        fx = fx > 0.f ? fx : 0.2f * fx;  fy = fy > 0.f ? fy : 0.2f * fy;
        fz = fz > 0.f ? fz : 0.2f * fz;  fw = fw > 0.f ? fw : 0.2f * fw;
        float q = fx * at.x + fy * at.y + fz * at.z + fw * at.w;
        q += __shfl_xor_sync(~0u, q, 1);
        q += __shfl_xor_sync(~0u, q, 2);
        float ex = __expf(q);
        den += ex;
        a0 = fmaf(ex, xv.x, a0);
        a1 = fmaf(ex, xv.y, a1);
        a2 = fmaf(ex, xv.z, a2);
        a3 = fmaf(ex, xv.w, a3);
    }
    float inv = 1.0f / den;
    float4 gb = ((const float4*)gat_bias)[sl];
    float o0 = fmaf(a0, inv, gb.x);
    float o1 = fmaf(a1, inv, gb.y);
    float o2 = fmaf(a2, inv, gb.z);
    float o3 = fmaf(a3, inv, gb.w);
    o0 = o0 > 0.f ? o0 : expm1f(o0);
    o1 = o1 > 0.f ? o1 : expm1f(o1);
    o2 = o2 > 0.f ? o2 : expm1f(o2);
    o3 = o3 > 0.f ? o3 : expm1f(o3);
    float4 h0v = ((const float4*)g_h0)[i * 16 + sl];
    ((float4*)out_h)[i * 16 + sl] =
        make_float4(h0v.x + o0, h0v.y + o1, h0v.z + o2, h0v.w + o3);
}

// ---------------- MLP tail: layer1 bf16-split wmma, layer2 SIMT ----------------
#define MS 66
__global__ __launch_bounds__(256)
void k_mlp(const float* __restrict__ h,
           const float* __restrict__ W1, const float* __restrict__ b1,
           const float* __restrict__ W2, const float* __restrict__ b2,
           float* __restrict__ logits) {
    __shared__ __align__(16) char sm[64 * MS * 2 * 2 * 2];
    __nv_bfloat16* W1h = (__nv_bfloat16*)sm;
    __nv_bfloat16* W1l = W1h + 64 * MS;
    __nv_bfloat16* Hh  = (__nv_bfloat16*)(sm + 64 * MS * 4);
    __nv_bfloat16* Hl  = Hh + 64 * MS;
    float* zs = (float*)(sm + 64 * MS * 4);
    __shared__ float W2s[64 * 10];
    __shared__ float b1s[64];
    __shared__ float b2s[16];

    int tid = threadIdx.x;
    int node0 = blockIdx.x * 64;
    int w = tid >> 5;
    int wr = w >> 1;
    int wc = w & 1;

    for (int idx = tid; idx < 64 * 64; idx += 256) {
        int r = idx >> 6, c = idx & 63;
        float wv = W1[idx];
        __nv_bfloat16 whi = __float2bfloat16(wv);
        W1h[r * MS + c] = whi;
        W1l[r * MS + c] = __float2bfloat16(wv - __bfloat162float(whi));
        int node = node0 + r;
        float hv = (node < NN) ? h[node * 64 + c] : 0.f;
        __nv_bfloat16 hhi = __float2bfloat16(hv);
        Hh[r * MS + c] = hhi;
        Hl[r * MS + c] = __float2bfloat16(hv - __bfloat162float(hhi));
    }
    for (int idx = tid; idx < 640; idx += 256) W2s[idx] = W2[idx];
    if (tid < 64) b1s[tid] = b1[tid];
    if (tid < 10) b2s[tid] = b2[tid];
    __syncthreads();

    wmma::fragment<wmma::accumulator, 16, 16, 16, float> acc[2];
    wmma::fill_fragment(acc[0], 0.f);
    wmma::fill_fragment(acc[1], 0.f);
    #pragma unroll
    for (int kf = 0; kf < 4; kf++) {
        wmma::fragment<wmma::matrix_a, 16, 16, 16, __nv_bfloat16, wmma::row_major> ah, al;
        wmma::load_matrix_sync(ah, &Hh[(wr * 16) * MS + kf * 16], MS);
        wmma::load_matrix_sync(al, &Hl[(wr * 16) * MS + kf * 16], MS);
        #pragma unroll
        for (int j = 0; j < 2; j++) {
            wmma::fragment<wmma::matrix_b, 16, 16, 16, __nv_bfloat16, wmma::row_major> bh, bl;
            wmma::load_matrix_sync(bh, &W1h[(kf * 16) * MS + wc * 32 + j * 16], MS);
            wmma::load_matrix_sync(bl, &W1l[(kf * 16) * MS + wc * 32 + j * 16], MS);
            wmma::mma_sync(acc[j], ah, bh, acc[j]);
            wmma::mma_sync(acc[j], al, bh, acc[j]);
            wmma::mma_sync(acc[j], ah, bl, acc[j]);
        }
    }
    __syncthreads();
    #pragma unroll
    for (int j = 0; j < 2; j++)
        wmma::store_matrix_sync(&zs[(wr * 16) * MS + wc * 32 + j * 16], acc[j], MS,
                                wmma::mem_row_major);
    __syncthreads();
    for (int idx = tid; idx < 64 * 64; idx += 256) {
        int r = idx >> 6, c = idx & 63;
        zs[r * MS + c] = fmaxf(zs[r * MS + c] + b1s[c], 0.f);
    }
    __syncthreads();
    for (int idx = tid; idx < 640; idx += 256) {
        int r = idx / 10, c = idx % 10;
        float s = b2s[c];
        #pragma unroll 8
        for (int k = 0; k < 64; k++) s += zs[r * MS + k] * W2s[k * 10 + c];
        int node = node0 + r;
        if (node < NN) logits[node * 10 + c] = s;
    }
}

// ---------------- launch: fork-join two streams inside the captured graph ----------------
static cudaStream_t s_csr = nullptr;
static cudaEvent_t  ev_f0 = nullptr, ev_fork = nullptr, ev_join = nullptr;
static void* a_cnt  = nullptr;
static void* a_stat = nullptr;

extern "C" void kernel_launch(void* const* d_in, const int* in_sizes, int n_in,
                              void* d_out, int out_size) {
    const float* x        = (const float*)d_in[0];
    const float* ew       = (const float*)d_in[1];
    const float* W_pre    = (const float*)d_in[2];
    const float* W_l      = (const float*)d_in[3];
    const float* b_l      = (const float*)d_in[4];
    const float* W_r      = (const float*)d_in[5];
    const float* b_r      = (const float*)d_in[6];
    const float* att      = (const float*)d_in[7];
    const float* W_edge   = (const float*)d_in[8];
    const float* gat_bias = (const float*)d_in[9];
    const float* W1       = (const float*)d_in[10];
    const float* b1       = (const float*)d_in[11];
    const float* W2       = (const float*)d_in[12];
    const float* b2       = (const float*)d_in[13];
    const void*  ei       = d_in[14];

    float* out_h      = (float*)d_out;
    float* out_logits = (float*)d_out + (size_t)NN * 64;

    // One-time host-side setup (first call is the non-captured correctness run).
    if (s_csr == nullptr) {
        cudaStreamCreateWithFlags(&s_csr, cudaStreamNonBlocking);
        cudaEventCreateWithFlags(&ev_f0, cudaEventDisableTiming);
        cudaEventCreateWithFlags(&ev_fork, cudaEventDisableTiming);
        cudaEventCreateWithFlags(&ev_join, cudaEventDisableTiming);
        cudaGetSymbolAddress(&a_cnt, g_cnt);
        cudaGetSymbolAddress(&a_stat, g_scan_stat);
    }

    // --- fork early: memsets run concurrently with k_detect ---
    cudaEventRecord(ev_f0, 0);
    cudaStreamWaitEvent(s_csr, ev_f0, 0);
    cudaMemsetAsync(a_cnt, 0, NN * sizeof(int), s_csr);
    cudaMemsetAsync(a_stat, 0, (NBLK + 1) * sizeof(unsigned), s_csr);

    k_detect<<<1, 32>>>((const int*)ei);
    cudaEventRecord(ev_fork, 0);
    cudaStreamWaitEvent(s_csr, ev_fork, 0);

    // --- side stream: CSR build chain ---
    k_hist<<<(EE / 2 + 255) / 256, 256, 0, s_csr>>>(ei);
    k_scan_lb<<<NBLK, 256, 0, s_csr>>>();
    k_scatter<<<(EE / 2 + 255) / 256, 256, 0, s_csr>>>(ei, ew);
    cudaEventRecord(ev_join, s_csr);

    // --- legacy stream (concurrent): GEMM chain ---
    k_build_wcat<<<128, 192>>>(W_pre, W_l, W_r);
    k_gemm_pre<<<(NPAD / 128), 256>>>(x, b_l, b_r);

    // --- join, then edge + mlp ---
    cudaStreamWaitEvent(0, ev_join, 0);
    k_edge<<<((NN + 1) / 2 * 32 + 255) / 256, 256>>>(W_edge, att, gat_bias, out_h);
    k_mlp<<<(NN + 63) / 64, 256>>>(out_h, W1, b1, W2, b2, out_logits);
}

// round 11
// speedup vs baseline: 1.4889x; 1.0117x over previous
#include <cuda_runtime.h>
#include <cuda_bf16.h>
#include <mma.h>
using namespace nvcuda;

#define NN 100000
#define NPAD 100096   // multiple of 128 so wmma stores never go OOB
#define EE 1600000
#define NBLK 98       // scan tiles: ceil(NN/1024)

// ---------------- scratch (static device globals; no allocation) ----------------
__device__ __align__(16) float g_h0[NPAD * 64];
__device__ __align__(16) float g_xl[NPAD * 64];
__device__ __align__(16) float g_xr[NPAD * 64];
__device__ __align__(16) float g_wcat[128 * 192];
__device__ int   g_cnt[NN];
__device__ int   g_rank[EE];
__device__ int   g_rowptr[NN + 1];
__device__ int2  g_csr[EE];
__device__ unsigned g_scan_stat[NBLK + 1];   // [0..NBLK-1] flagged prefix, [NBLK] tile counter

// int64 edge_index => odd 32-bit words are all zero (node ids < 2^31)
__device__ __forceinline__ int detect64(const int* __restrict__ ei32) {
    return ((ei32[1] | ei32[3] | ei32[5] | ei32[7]) == 0);
}

// ---------------- composite weight: wcat = [W_pre | W_pre@W_l | W_pre@W_r] ----------------
__global__ void k_build_wcat(const float* __restrict__ W_pre,
                             const float* __restrict__ W_l,
                             const float* __restrict__ W_r) {
    int k = blockIdx.x;
    int j = threadIdx.x;
    float v;
    if (j < 64) {
        v = W_pre[k * 64 + j];
    } else {
        const float* W = (j < 128) ? W_l : W_r;
        int c = (j < 128) ? (j - 64) : (j - 128);
        float s = 0.f;
        #pragma unroll 8
        for (int m = 0; m < 64; m++) s += W_pre[k * 64 + m] * W[m * 64 + c];
        v = s;
    }
    g_wcat[k * 192 + j] = v;
}

// ---------------- bf16 3-term split tensor-core GEMM (pre) ----------------
#define A_STRIDE 40
#define B_STRIDE 200
__global__ __launch_bounds__(256, 1)
void k_gemm_pre(const float* __restrict__ x,
                const float* __restrict__ b_l,
                const float* __restrict__ b_r) {
    __shared__ __align__(16) char smem[2 * 128 * A_STRIDE * 2 + 2 * 32 * B_STRIDE * 2];
    __nv_bfloat16* Ah = (__nv_bfloat16*)smem;
    __nv_bfloat16* Al = Ah + 128 * A_STRIDE;
    __nv_bfloat16* Bh = (__nv_bfloat16*)(smem + 2 * 128 * A_STRIDE * 2);
    __nv_bfloat16* Bl = Bh + 32 * B_STRIDE;
    float* biasT = (float*)smem;

    int tid = threadIdx.x;
    int node0 = blockIdx.x * 128;
    int w = tid >> 5;
    int wr = w >> 1;
    int wc = w & 1;

    for (int idx = tid; idx < 16 * B_STRIDE; idx += 256) {
        int c = idx % B_STRIDE;
        float v = 0.f;
        if (c >= 64 && c < 128)       v = b_l[c - 64];
        else if (c >= 128 && c < 192) v = b_r[c - 128];
        biasT[idx] = v;
    }
    __syncthreads();

    wmma::fragment<wmma::accumulator, 16, 16, 16, float> acc[2][6];
    #pragma unroll
    for (int i = 0; i < 2; i++)
        #pragma unroll
        for (int j = 0; j < 6; j++)
            wmma::load_matrix_sync(acc[i][j], &biasT[wc * 96 + j * 16], B_STRIDE,
                                   wmma::mem_row_major);
    __syncthreads();

    for (int kc = 0; kc < 4; kc++) {
        for (int idx = tid; idx < 128 * 8; idx += 256) {
            int rr = idx >> 3, q = idx & 7;
            int node = node0 + rr;
            float4 v = make_float4(0.f, 0.f, 0.f, 0.f);
            if (node < NN) v = *(const float4*)&x[node * 128 + kc * 32 + q * 4];
            __nv_bfloat16* ph = &Ah[rr * A_STRIDE + q * 4];
            __nv_bfloat16* pl = &Al[rr * A_STRIDE + q * 4];
            float vv[4] = {v.x, v.y, v.z, v.w};
            #pragma unroll
            for (int u = 0; u < 4; u++) {
                __nv_bfloat16 hi = __float2bfloat16(vv[u]);
                ph[u] = hi;
                pl[u] = __float2bfloat16(vv[u] - __bfloat162float(hi));
            }
        }
        for (int idx = tid; idx < 32 * 48; idx += 256) {
            int rr = idx / 48, q = idx % 48;
            float4 v = *(const float4*)&g_wcat[(kc * 32 + rr) * 192 + q * 4];
            __nv_bfloat16* ph = &Bh[rr * B_STRIDE + q * 4];
            __nv_bfloat16* pl = &Bl[rr * B_STRIDE + q * 4];
            float vv[4] = {v.x, v.y, v.z, v.w};
            #pragma unroll
            for (int u = 0; u < 4; u++) {
                __nv_bfloat16 hi = __float2bfloat16(vv[u]);
                ph[u] = hi;
                pl[u] = __float2bfloat16(vv[u] - __bfloat162float(hi));
            }
        }
        __syncthreads();

        #pragma unroll
        for (int kf = 0; kf < 2; kf++) {
            wmma::fragment<wmma::matrix_a, 16, 16, 16, __nv_bfloat16, wmma::row_major> ah[2], al[2];
            #pragma unroll
            for (int i = 0; i < 2; i++) {
                wmma::load_matrix_sync(ah[i], &Ah[(wr * 32 + i * 16) * A_STRIDE + kf * 16], A_STRIDE);
                wmma::load_matrix_sync(al[i], &Al[(wr * 32 + i * 16) * A_STRIDE + kf * 16], A_STRIDE);
            }
            #pragma unroll
            for (int j = 0; j < 6; j++) {
                wmma::fragment<wmma::matrix_b, 16, 16, 16, __nv_bfloat16, wmma::row_major> bh, bl;
                wmma::load_matrix_sync(bh, &Bh[(kf * 16) * B_STRIDE + wc * 96 + j * 16], B_STRIDE);
                wmma::load_matrix_sync(bl, &Bl[(kf * 16) * B_STRIDE + wc * 96 + j * 16], B_STRIDE);
                #pragma unroll
                for (int i = 0; i < 2; i++) {
                    wmma::mma_sync(acc[i][j], ah[i], bh, acc[i][j]);
                    wmma::mma_sync(acc[i][j], al[i], bh, acc[i][j]);
                    wmma::mma_sync(acc[i][j], ah[i], bl, acc[i][j]);
                }
            }
        }
        __syncthreads();
    }

    #pragma unroll
    for (int j = 0; j < 6; j++) {
        int CT = wc * 6 + j;
        float* base; int cofs;
        if (CT < 4)      { base = g_h0; cofs = CT * 16; }
        else if (CT < 8) { base = g_xl; cofs = (CT - 4) * 16; }
        else             { base = g_xr; cofs = (CT - 8) * 16; }
        #pragma unroll
        for (int i = 0; i < 2; i++)
            wmma::store_matrix_sync(&base[(size_t)(node0 + wr * 32 + i * 16) * 64 + cofs],
                                    acc[i][j], 64, wmma::mem_row_major);
    }
}

// ---------------- histogram: in-degree + per-edge rank, 2 edges/thread ----------------
__global__ void k_hist(const void* __restrict__ ei) {
    int e = (blockIdx.x * blockDim.x + threadIdx.x) * 2;
    if (e >= EE) return;
    int d0, d1;
    if (detect64((const int*)ei)) {
        d0 = (int)((const long long*)ei)[EE + e];
        d1 = (int)((const long long*)ei)[EE + e + 1];
    } else {
        int2 dd = *(const int2*)((const int*)ei + EE + e);
        d0 = dd.x; d1 = dd.y;
    }
    g_rank[e]     = atomicAdd(&g_cnt[d0], 1);
    g_rank[e + 1] = atomicAdd(&g_cnt[d1], 1);
}

// ---------------- single-kernel decoupled-lookback exclusive scan ----------------
__global__ __launch_bounds__(256)
void k_scan_lb() {
    __shared__ int s_tile;
    __shared__ int s_prefix;
    __shared__ int wsum[8];
    int tid = threadIdx.x;
    if (tid == 0) s_tile = (int)atomicAdd(&g_scan_stat[NBLK], 1u);
    __syncthreads();
    int tile = s_tile;

    int idx = tile * 1024 + tid * 4;
    int v[4];
    #pragma unroll
    for (int j = 0; j < 4; j++) {
        int k = idx + j;
        v[j] = (k < NN) ? g_cnt[k] : 0;
    }
    int s = v[0] + v[1] + v[2] + v[3];
    int lane = tid & 31, wid = tid >> 5;
    int xval = s;
    for (int o = 1; o < 32; o <<= 1) {
        int y = __shfl_up_sync(~0u, xval, o);
        if (lane >= o) xval += y;
    }
    if (lane == 31) wsum[wid] = xval;
    __syncthreads();
    if (wid == 0) {
        int w = (lane < 8) ? wsum[lane] : 0;
        for (int o = 1; o < 8; o <<= 1) {
            int y = __shfl_up_sync(~0u, w, o);
            if (lane >= o) w += y;
        }
        if (lane < 8) wsum[lane] = w;
    }
    __syncthreads();
    int total = wsum[7];

    if (tid == 0) {
        if (tile > 0) {
            atomicExch(&g_scan_stat[tile], (unsigned)total | (1u << 30));
            int run = 0;
            int j = tile - 1;
            while (true) {
                unsigned st = *(volatile unsigned*)&g_scan_stat[j];
                unsigned fl = st >> 30;
                if (fl == 0u) continue;
                run += (int)(st & 0x3FFFFFFFu);
                if (fl >= 2u) break;
                j--;
            }
            s_prefix = run;
            atomicExch(&g_scan_stat[tile], (unsigned)(run + total) | (2u << 30));
        } else {
            s_prefix = 0;
            atomicExch(&g_scan_stat[0], (unsigned)total | (2u << 30));
        }
        if (tile == NBLK - 1) g_rowptr[NN] = s_prefix + total;
    }
    __syncthreads();

    int excl = s_prefix + xval - s + (wid > 0 ? wsum[wid - 1] : 0);
    #pragma unroll
    for (int j = 0; j < 4; j++) {
        int k = idx + j;
        if (k < NN) g_rowptr[k] = excl;
        excl += v[j];
    }
}

// ---------------- scatter edges into CSR: atomic-free (rank precomputed) ----------------
__global__ void k_scatter(const void* __restrict__ ei, const float* __restrict__ ew) {
    int e = (blockIdx.x * blockDim.x + threadIdx.x) * 2;
    if (e >= EE) return;
    int s0, s1, d0, d1;
    if (detect64((const int*)ei)) {
        const long long* e64 = (const long long*)ei;
        s0 = (int)e64[e];      s1 = (int)e64[e + 1];
        d0 = (int)e64[EE + e]; d1 = (int)e64[EE + e + 1];
    } else {
        const int* e32 = (const int*)ei;
        int2 ss = *(const int2*)(e32 + e);
        int2 dd = *(const int2*)(e32 + EE + e);
        s0 = ss.x; s1 = ss.y; d0 = dd.x; d1 = dd.y;
    }
    float2 w = *(const float2*)&ew[e];
    int2 rk = *(const int2*)&g_rank[e];
    g_csr[g_rowptr[d0] + rk.x] = make_int2(s0, __float_as_int(w.x));
    g_csr[g_rowptr[d1] + rk.y] = make_int2(s1, __float_as_int(w.y));
}

// ---------------- fused edge + MLP: 16 nodes/block (8 warps, 2 nodes/warp) ----------------
// All edge-phase shuffles use the HALF-WARP mask: the two halves of a warp
// process different nodes (different deg), so full-mask shfl_sync is UB and
// deadlocks against the later __syncthreads().
#define HS 68
__global__ __launch_bounds__(256)
void k_edge_mlp(const float* __restrict__ W_edge,
                const float* __restrict__ att,
                const float* __restrict__ gat_bias,
                const float* __restrict__ W1, const float* __restrict__ b1,
                const float* __restrict__ W2, const float* __restrict__ b2,
                float* __restrict__ out_h,
                float* __restrict__ out_logits) {
    __shared__ __align__(16) float W1s[64 * 64];
    __shared__ __align__(16) float hs[16 * HS];
    __shared__ __align__(16) float zs[16 * HS];
    __shared__ float W2s[64 * 10];
    __shared__ float b1s[64];
    __shared__ float b2s[16];

    int tid = threadIdx.x;
    int warp = tid >> 5;
    int lane = tid & 31;
    int half = lane >> 4, sl = lane & 15;
    unsigned hmask = 0xFFFFu << (half * 16);      // lanes sharing this node
    int local = (warp << 1) + half;               // 0..15
    int i = blockIdx.x * 16 + local;              // NN = 6250*16 exactly

    // ---- edge phase ----
    {
        const float4* xl4 = (const float4*)g_xl;
        float4 xr = ((const float4*)g_xr)[i * 16 + sl];
        float4 we = ((const float4*)W_edge)[sl];
        float4 at = ((const float4*)att)[sl];

        int start = g_rowptr[i];
        int deg   = g_rowptr[i + 1] - start;

        float den = 0.f, sw = 0.f;
        float a0 = 0.f, a1 = 0.f, a2 = 0.f, a3 = 0.f;

        int t = 0;
        for (; t + 2 <= deg; t += 2) {
            int2 p0 = g_csr[start + t];
            int2 p1 = g_csr[start + t + 1];
            float4 x0 = xl4[p0.x * 16 + sl];
            float4 x1 = xl4[p1.x * 16 + sl];
            float ea0 = __int_as_float(p0.y), ea1 = __int_as_float(p1.y);
            sw += ea0 + ea1;

            float f0x = fmaf(ea0, we.x, x0.x + xr.x);
            float f0y = fmaf(ea0, we.y, x0.y + xr.y);
            float f0z = fmaf(ea0, we.z, x0.z + xr.z);
            float f0w = fmaf(ea0, we.w, x0.w + xr.w);
            float f1x = fmaf(ea1, we.x, x1.x + xr.x);
            float f1y = fmaf(ea1, we.y, x1.y + xr.y);
            float f1z = fmaf(ea1, we.z, x1.z + xr.z);
            float f1w = fmaf(ea1, we.w, x1.w + xr.w);
            f0x = f0x > 0.f ? f0x : 0.2f * f0x;  f0y = f0y > 0.f ? f0y : 0.2f * f0y;
            f0z = f0z > 0.f ? f0z : 0.2f * f0z;  f0w = f0w > 0.f ? f0w : 0.2f * f0w;
            f1x = f1x > 0.f ? f1x : 0.2f * f1x;  f1y = f1y > 0.f ? f1y : 0.2f * f1y;
            f1z = f1z > 0.f ? f1z : 0.2f * f1z;  f1w = f1w > 0.f ? f1w : 0.2f * f1w;
            float q0 = f0x * at.x + f0y * at.y + f0z * at.z + f0w * at.w;
            float q1 = f1x * at.x + f1y * at.y + f1z * at.z + f1w * at.w;
            q0 += __shfl_xor_sync(hmask, q0, 1);
            q1 += __shfl_xor_sync(hmask, q1, 1);
            q0 += __shfl_xor_sync(hmask, q0, 2);
            q1 += __shfl_xor_sync(hmask, q1, 2);
            float e0 = __expf(q0);
            float e1 = __expf(q1);
            den += e0 + e1;
            a0 = fmaf(e0, x0.x, a0); a0 = fmaf(e1, x1.x, a0);
            a1 = fmaf(e0, x0.y, a1); a1 = fmaf(e1, x1.y, a1);
            a2 = fmaf(e0, x0.z, a2); a2 = fmaf(e1, x1.z, a2);
            a3 = fmaf(e0, x0.w, a3); a3 = fmaf(e1, x1.w, a3);
        }
        if (t < deg) {
            int2 p = g_csr[start + t];
            float ea = __int_as_float(p.y);
            sw += ea;
            float4 xv = xl4[p.x * 16 + sl];
            float fx = fmaf(ea, we.x, xv.x + xr.x);
            float fy = fmaf(ea, we.y, xv.y + xr.y);
            float fz = fmaf(ea, we.z, xv.z + xr.z);
            float fw = fmaf(ea, we.w, xv.w + xr.w);
            fx = fx > 0.f ? fx : 0.2f * fx;  fy = fy > 0.f ? fy : 0.2f * fy;
            fz = fz > 0.f ? fz : 0.2f * fz;  fw = fw > 0.f ? fw : 0.2f * fw;
            float q = fx * at.x + fy * at.y + fz * at.z + fw * at.w;
            q += __shfl_xor_sync(hmask, q, 1);
            q += __shfl_xor_sync(hmask, q, 2);
            float ex = __expf(q);
            den += ex;
            a0 = fmaf(ex, xv.x, a0);
            a1 = fmaf(ex, xv.y, a1);
            a2 = fmaf(ex, xv.z, a2);
            a3 = fmaf(ex, xv.w, a3);
        }
        {   // self loop with mean edge weight
            float ea = sw / fmaxf((float)deg, 1.0f);
            float4 xv = xl4[i * 16 + sl];
            float fx = fmaf(ea, we.x, xv.x + xr.x);
            float fy = fmaf(ea, we.y, xv.y + xr.y);
            float fz = fmaf(ea, we.z, xv.z + xr.z);
            float fw = fmaf(ea, we.w, xv.w + xr.w);
            fx = fx > 0.f ? fx : 0.2f * fx;  fy = fy > 0.f ? fy : 0.2f * fy;
            fz = fz > 0.f ? fz : 0.2f * fz;  fw = fw > 0.f ? fw : 0.2f * fw;
            float q = fx * at.x + fy * at.y + fz * at.z + fw * at.w;
            q += __shfl_xor_sync(hmask, q, 1);
            q += __shfl_xor_sync(hmask, q, 2);
            float ex = __expf(q);
            den += ex;
            a0 = fmaf(ex, xv.x, a0);
            a1 = fmaf(ex, xv.y, a1);
            a2 = fmaf(ex, xv.z, a2);
            a3 = fmaf(ex, xv.w, a3);
        }
        float inv = 1.0f / den;
        float4 gb = ((const float4*)gat_bias)[sl];
        float o0 = fmaf(a0, inv, gb.x);
        float o1 = fmaf(a1, inv, gb.y);
        float o2 = fmaf(a2, inv, gb.z);
        float o3 = fmaf(a3, inv, gb.w);
        o0 = o0 > 0.f ? o0 : expm1f(o0);
        o1 = o1 > 0.f ? o1 : expm1f(o1);
        o2 = o2 > 0.f ? o2 : expm1f(o2);
        o3 = o3 > 0.f ? o3 : expm1f(o3);
        float4 h0v = ((const float4*)g_h0)[i * 16 + sl];
        float4 hv = make_float4(h0v.x + o0, h0v.y + o1, h0v.z + o2, h0v.w + o3);
        ((float4*)out_h)[i * 16 + sl] = hv;
        *(float4*)&hs[local * HS + sl * 4] = hv;
    }

    // ---- stage weights ----
    for (int idx = tid; idx < 64 * 64; idx += 256) W1s[idx] = W1[idx];
    for (int idx = tid; idx < 640; idx += 256)     W2s[idx] = W2[idx];
    if (tid < 64) b1s[tid] = b1[tid];
    if (tid < 10) b2s[tid] = b2[tid];
    __syncthreads();

    // ---- layer 1: z = relu(h @ W1 + b1), 16x64 ----
    {
        int r = tid >> 4;             // 0..15
        int cq = (tid & 15) * 4;      // 0..60
        float acc0 = b1s[cq], acc1 = b1s[cq + 1], acc2 = b1s[cq + 2], acc3 = b1s[cq + 3];
        #pragma unroll 8
        for (int k = 0; k < 64; k++) {
            float hv = hs[r * HS + k];
            float4 wv = *(const float4*)&W1s[k * 64 + cq];
            acc0 = fmaf(hv, wv.x, acc0);
            acc1 = fmaf(hv, wv.y, acc1);
            acc2 = fmaf(hv, wv.z, acc2);
            acc3 = fmaf(hv, wv.w, acc3);
        }
        zs[r * HS + cq]     = fmaxf(acc0, 0.f);
        zs[r * HS + cq + 1] = fmaxf(acc1, 0.f);
        zs[r * HS + cq + 2] = fmaxf(acc2, 0.f);
        zs[r * HS + cq + 3] = fmaxf(acc3, 0.f);
    }
    __syncthreads();

    // ---- layer 2: logits = z @ W2 + b2, 16x10 ----
    if (tid < 160) {
        int r = tid / 10, c = tid % 10;
        float s = b2s[c];
        #pragma unroll 8
        for (int k = 0; k < 64; k++) s = fmaf(zs[r * HS + k], W2s[k * 10 + c], s);
        out_logits[(blockIdx.x * 16 + r) * 10 + c] = s;
    }
}

// ---------------- launch: fork-join two streams inside the captured graph ----------------
static cudaStream_t s_csr = nullptr;
static cudaEvent_t  ev_f0 = nullptr, ev_join = nullptr;
static void* a_cnt  = nullptr;
static void* a_stat = nullptr;

extern "C" void kernel_launch(void* const* d_in, const int* in_sizes, int n_in,
                              void* d_out, int out_size) {
    const float* x        = (const float*)d_in[0];
    const float* ew       = (const float*)d_in[1];
    const float* W_pre    = (const float*)d_in[2];
    const float* W_l      = (const float*)d_in[3];
    const float* b_l      = (const float*)d_in[4];
    const float* W_r      = (const float*)d_in[5];
    const float* b_r      = (const float*)d_in[6];
    const float* att      = (const float*)d_in[7];
    const float* W_edge   = (const float*)d_in[8];
    const float* gat_bias = (const float*)d_in[9];
    const float* W1       = (const float*)d_in[10];
    const float* b1       = (const float*)d_in[11];
    const float* W2       = (const float*)d_in[12];
    const float* b2       = (const float*)d_in[13];
    const void*  ei       = d_in[14];

    float* out_h      = (float*)d_out;
    float* out_logits = (float*)d_out + (size_t)NN * 64;

    if (s_csr == nullptr) {
        cudaStreamCreateWithFlags(&s_csr, cudaStreamNonBlocking);
        cudaEventCreateWithFlags(&ev_f0, cudaEventDisableTiming);
        cudaEventCreateWithFlags(&ev_join, cudaEventDisableTiming);
        cudaGetSymbolAddress(&a_cnt, g_cnt);
        cudaGetSymbolAddress(&a_stat, g_scan_stat);
    }

    // --- fork immediately ---
    cudaEventRecord(ev_f0, 0);
    cudaStreamWaitEvent(s_csr, ev_f0, 0);

    // --- side stream: CSR build chain ---
    cudaMemsetAsync(a_cnt, 0, NN * sizeof(int), s_csr);
    cudaMemsetAsync(a_stat, 0, (NBLK + 1) * sizeof(unsigned), s_csr);
    k_hist<<<(EE / 2 + 255) / 256, 256, 0, s_csr>>>(ei);
    k_scan_lb<<<NBLK, 256, 0, s_csr>>>();
    k_scatter<<<(EE / 2 + 255) / 256, 256, 0, s_csr>>>(ei, ew);
    cudaEventRecord(ev_join, s_csr);

    // --- legacy stream (concurrent): GEMM chain ---
    k_build_wcat<<<128, 192>>>(W_pre, W_l, W_r);
    k_gemm_pre<<<(NPAD / 128), 256>>>(x, b_l, b_r);

    // --- join, then fused edge + MLP ---
    cudaStreamWaitEvent(0, ev_join, 0);
    k_edge_mlp<<<NN / 16, 256>>>(W_edge, att, gat_bias, W1, b1, W2, b2,
                                 out_h, out_logits);
}